// round 2
// baseline (speedup 1.0000x reference)
#include <cuda_runtime.h>
#include <stdint.h>

#define N_NODES 50000
#define N_EDGES 625000
#define D 128
#define BM 64

// ---------------- scratch (no allocs allowed) ----------------
__device__ int   g_deg_out[N_NODES];              // histogram over receivers (+self added at use)
__device__ int   g_deg_in[N_NODES];               // histogram over senders
__device__ float g_agg[(size_t)N_NODES * D];      // 25.6 MB, L2-resident
__device__ int   g_is64;                          // 1 if indices are int64

// ---------------- K0: zero scratch + dtype probe ----------------
__global__ void k_init(const void* __restrict__ senders) {
    size_t i = (size_t)blockIdx.x * blockDim.x + threadIdx.x;
    size_t total = (size_t)N_NODES * D;
    size_t stride = (size_t)gridDim.x * blockDim.x;
    for (size_t j = i; j < total; j += stride) g_agg[j] = 0.0f;
    if (i < N_NODES) { g_deg_out[i] = 0; g_deg_in[i] = 0; }
    if (i == 0) {
        // int64 values are in [0, 50000): high 32-bit words are all zero.
        // For int32 data these words are random node ids -> P(all zero) ~ 0.
        const int* w = (const int*)senders;
        int is64 = 1;
        #pragma unroll
        for (int k = 0; k < 16; k++) if (w[2 * k + 1] != 0) is64 = 0;
        g_is64 = is64;
    }
}

__device__ __forceinline__ int load_idx(const void* p, int e, int is64) {
    return is64 ? (int)((const long long*)p)[e] : ((const int*)p)[e];
}

// ---------------- K1: degree histograms ----------------
__global__ void k_deg(const void* __restrict__ senders, const void* __restrict__ receivers) {
    int e = blockIdx.x * blockDim.x + threadIdx.x;
    if (e >= N_EDGES) return;
    int is64 = g_is64;
    int s = load_idx(senders, e, is64);
    int r = load_idx(receivers, e, is64);
    atomicAdd(&g_deg_in[s], 1);
    atomicAdd(&g_deg_out[r], 1);
}

// ---------------- K2: edge scatter (1 warp per edge, v4 reductions) ----------------
__global__ void __launch_bounds__(256) k_scatter(const float* __restrict__ x,
                                                 const void* __restrict__ senders,
                                                 const void* __restrict__ receivers) {
    int warp = (blockIdx.x * blockDim.x + threadIdx.x) >> 5;
    int lane = threadIdx.x & 31;
    if (warp >= N_EDGES) return;
    int is64 = g_is64;
    int s = load_idx(senders, warp, is64);
    int r = load_idx(receivers, warp, is64);
    float scale = rsqrtf((float)(g_deg_out[s] + 1));   // out_degree_norm[sender]
    float4 v = ((const float4*)(x + (size_t)s * D))[lane];
    v.x *= scale; v.y *= scale; v.z *= scale; v.w *= scale;
    float* dst = g_agg + (size_t)r * D + lane * 4;
    asm volatile("red.global.add.v4.f32 [%0], {%1,%2,%3,%4};"
                 :: "l"(dst), "f"(v.x), "f"(v.y), "f"(v.z), "f"(v.w) : "memory");
}

// ---------------- K3: fused self-loop + scaling + GEMM ----------------
// out[n][j] = b[j] + sum_{k<128} x[n][k] W[j][k]
//                  + sum_{k<128} a[n][k] W[j][128+k]
// a[n] = (agg[n] + x[n]*rsqrt(do)) * rsqrt(di) / do ,  do = deg_out[n]+1, di = deg_in[n]+1
__global__ void __launch_bounds__(256, 1)
k_gemm(const float* __restrict__ x, const float* __restrict__ W,
       const float* __restrict__ bias, float* __restrict__ out) {
    extern __shared__ float sm[];
    float* sW  = sm;                 // [256][128] k-major      (32768 floats)
    float* sC  = sm + 32768;         // [BM][260] padded rows   (16640 floats)
    float* sB  = sC + BM * 260;      // [128]
    float* sSO = sB + 128;           // [BM] self-loop scale
    float* sM  = sSO + BM;           // [BM] post scale

    int tid = threadIdx.x;
    int n0  = blockIdx.x * BM;

    // per-row scales
    if (tid < BM) {
        int n = n0 + tid;
        if (n >= N_NODES) n = 0;
        float dout = (float)(g_deg_out[n] + 1);
        float din  = (float)(g_deg_in[n] + 1);
        sSO[tid] = rsqrtf(dout);
        sM[tid]  = rsqrtf(din) / dout;
    }
    if (tid < 128) sB[tid] = bias[tid];

    // load W into k-major smem: sW[k*128 + j]
    for (int idx = tid; idx < 128 * 64; idx += 256) {
        int j  = idx & 127;          // output col
        int kq = idx >> 7;           // k/4
        float4 w = ((const float4*)W)[j * 64 + kq];
        int kb = kq * 4;
        sW[(kb + 0) * 128 + j] = w.x;
        sW[(kb + 1) * 128 + j] = w.y;
        sW[(kb + 2) * 128 + j] = w.z;
        sW[(kb + 3) * 128 + j] = w.w;
    }
    __syncthreads();   // sSO/sM ready before combined-tile build

    // build combined tile [BM][256]: k<128 -> x, k>=128 -> scaled aggregate
    for (int idx = tid; idx < BM * 64; idx += 256) {
        int row = idx >> 6;
        int q   = idx & 63;          // float4 index within 256-float row
        int n   = n0 + row;
        if (n >= N_NODES) n = 0;
        float4 v;
        if (q < 32) {
            v = ((const float4*)(x + (size_t)n * D))[q];
        } else {
            int qq = q - 32;
            float4 a  = ((const float4*)(g_agg + (size_t)n * D))[qq];
            float4 xv = ((const float4*)(x + (size_t)n * D))[qq];
            float so = sSO[row], m = sM[row];
            v.x = (a.x + xv.x * so) * m;
            v.y = (a.y + xv.y * so) * m;
            v.z = (a.z + xv.z * so) * m;
            v.w = (a.w + xv.w * so) * m;
        }
        *(float4*)(sC + row * 260 + q * 4) = v;
    }
    __syncthreads();

    // 4x8 register micro-tile per thread; 16x16 thread grid
    int tx = tid & 15;               // col group: cols tx*8 .. tx*8+7
    int ty = tid >> 4;               // row group: rows ty*4 .. ty*4+3
    float acc[4][8];
    #pragma unroll
    for (int i = 0; i < 4; i++)
        #pragma unroll
        for (int j = 0; j < 8; j++) acc[i][j] = 0.0f;

    const float* cBase = sC + (ty * 4) * 260;
    #pragma unroll 4
    for (int k = 0; k < 256; k += 4) {
        float cr[16];
        #pragma unroll
        for (int i = 0; i < 4; i++)
            *(float4*)(cr + 4 * i) = *(const float4*)(cBase + i * 260 + k);
        #pragma unroll
        for (int kk = 0; kk < 4; kk++) {
            const float* wrow = sW + (k + kk) * 128 + tx * 8;
            float4 wlo = *(const float4*)(wrow);
            float4 whi = *(const float4*)(wrow + 4);
            float w[8] = {wlo.x, wlo.y, wlo.z, wlo.w, whi.x, whi.y, whi.z, whi.w};
            #pragma unroll
            for (int i = 0; i < 4; i++) {
                float c = cr[i * 4 + kk];
                #pragma unroll
                for (int j = 0; j < 8; j++) acc[i][j] += c * w[j];
            }
        }
    }

    // epilogue: add bias, store
    #pragma unroll
    for (int i = 0; i < 4; i++) {
        int n = n0 + ty * 4 + i;
        if (n >= N_NODES) continue;
        float* o = out + (size_t)n * D + tx * 8;
        float4 r0, r1;
        r0.x = acc[i][0] + sB[tx * 8 + 0];
        r0.y = acc[i][1] + sB[tx * 8 + 1];
        r0.z = acc[i][2] + sB[tx * 8 + 2];
        r0.w = acc[i][3] + sB[tx * 8 + 3];
        r1.x = acc[i][4] + sB[tx * 8 + 4];
        r1.y = acc[i][5] + sB[tx * 8 + 5];
        r1.z = acc[i][6] + sB[tx * 8 + 6];
        r1.w = acc[i][7] + sB[tx * 8 + 7];
        *(float4*)(o)     = r0;
        *(float4*)(o + 4) = r1;
    }
}

// ---------------- launch ----------------
extern "C" void kernel_launch(void* const* d_in, const int* in_sizes, int n_in,
                              void* d_out, int out_size) {
    const float* x   = (const float*)d_in[0];
    const void*  snd = d_in[1];
    const void*  rcv = d_in[2];
    const float* W   = nullptr;
    const float* b   = nullptr;
    for (int i = 3; i < n_in; i++) {               // skip scalar n_nodes wherever it sits
        if (in_sizes[i] == 2 * D * D) W = (const float*)d_in[i];
        else if (in_sizes[i] == D)    b = (const float*)d_in[i];
    }
    float* out = (float*)d_out;

    // K0: zero agg + degrees, probe index dtype
    k_init<<<(N_NODES * D + 255) / 256, 256>>>(snd);
    // K1: degree histograms
    k_deg<<<(N_EDGES + 255) / 256, 256>>>(snd, rcv);
    // K2: scatter (1 warp/edge, 8 edges per 256-thread block)
    k_scatter<<<N_EDGES / 8, 256>>>(x, snd, rcv);
    // K3: fused scale + GEMM
    const int smem_bytes = (32768 + BM * 260 + 128 + BM + BM) * (int)sizeof(float);
    cudaFuncSetAttribute(k_gemm, cudaFuncAttributeMaxDynamicSharedMemorySize, smem_bytes);
    k_gemm<<<(N_NODES + BM - 1) / BM, 256, smem_bytes>>>(x, W, b, out);
}

// round 4
// speedup vs baseline: 1.7897x; 1.7897x over previous
#include <cuda_runtime.h>
#include <cuda_bf16.h>
#include <stdint.h>

#define N_NODES 50000
#define N_EDGES 625000
#define D 128

// ---------------- scratch (no allocs allowed) ----------------
__device__ int   g_deg_out[N_NODES];
__device__ int   g_deg_in[N_NODES];
__device__ float g_agg[(size_t)N_NODES * D];      // 25.6 MB, L2-resident
__device__ int   g_is64;

// ---------------- K0: zero scratch + dtype probe ----------------
__global__ void k_init(const void* __restrict__ senders) {
    size_t i = (size_t)blockIdx.x * blockDim.x + threadIdx.x;
    size_t total = (size_t)N_NODES * D;
    size_t stride = (size_t)gridDim.x * blockDim.x;
    for (size_t j = i; j < total; j += stride) g_agg[j] = 0.0f;
    if (i < N_NODES) { g_deg_out[i] = 0; g_deg_in[i] = 0; }
    if (i == 0) {
        // int64 indices in [0, 50000): high words all zero. int32 data: ~never.
        const int* w = (const int*)senders;
        int is64 = 1;
        #pragma unroll
        for (int k = 0; k < 16; k++) if (w[2 * k + 1] != 0) is64 = 0;
        g_is64 = is64;
    }
}

__device__ __forceinline__ int load_idx(const void* p, int e, int is64) {
    return is64 ? (int)((const long long*)p)[e] : ((const int*)p)[e];
}

// ---------------- K1: degree histograms ----------------
__global__ void k_deg(const void* __restrict__ senders, const void* __restrict__ receivers) {
    int e = blockIdx.x * blockDim.x + threadIdx.x;
    if (e >= N_EDGES) return;
    int is64 = g_is64;
    int s = load_idx(senders, e, is64);
    int r = load_idx(receivers, e, is64);
    atomicAdd(&g_deg_in[s], 1);
    atomicAdd(&g_deg_out[r], 1);
}

// ---------------- K2: edge scatter (1 warp per edge, v4 reductions) ----------------
__global__ void __launch_bounds__(256) k_scatter(const float* __restrict__ x,
                                                 const void* __restrict__ senders,
                                                 const void* __restrict__ receivers) {
    int warp = (blockIdx.x * blockDim.x + threadIdx.x) >> 5;
    int lane = threadIdx.x & 31;
    if (warp >= N_EDGES) return;
    int is64 = g_is64;
    int s = load_idx(senders, warp, is64);
    int r = load_idx(receivers, warp, is64);
    float scale = rsqrtf((float)(g_deg_out[s] + 1));
    float4 v = ((const float4*)(x + (size_t)s * D))[lane];
    v.x *= scale; v.y *= scale; v.z *= scale; v.w *= scale;
    float* dst = g_agg + (size_t)r * D + lane * 4;
    asm volatile("red.global.add.v4.f32 [%0], {%1,%2,%3,%4};"
                 :: "l"(dst), "f"(v.x), "f"(v.y), "f"(v.z), "f"(v.w) : "memory");
}

// ---------------- K3: split-bf16 GEMM via mma.sync (HMMA) ----------------
// out = [x | a] @ W^T + b ,  a = (agg + x*rsqrt(do)) * rsqrt(di)/do
// v = hi + lo (bf16 each); D = Ahi*Whi + Ahi*Wlo + Alo*Whi, f32 accum.
// CTA tile: M=128, N=128, K=256 (half0 = x, half1 = a). 8 warps, each 64Mx32N.

#define A_PITCH 136            // halves per A row (128 + 8 pad)
#define W_PITCH 264            // halves per W row (256 + 8 pad)
#define OFF_WHI  0
#define OFF_WLO  (OFF_WHI + 128 * W_PITCH * 2)       // 67584
#define OFF_AHI  (OFF_WLO + 128 * W_PITCH * 2)       // 135168
#define OFF_ALO  (OFF_AHI + 128 * A_PITCH * 2)       // 169984
#define OFF_BIAS (OFF_ALO + 128 * A_PITCH * 2)       // 204800
#define OFF_SO   (OFF_BIAS + 512)
#define OFF_MM   (OFF_SO + 512)
#define SMEM_K3  (OFF_MM + 512)                      // 206336 bytes

__device__ __forceinline__ void split_store4(char* hi_base, char* lo_base, int half_off, float4 v) {
    __nv_bfloat16 h0 = __float2bfloat16(v.x);
    __nv_bfloat16 h1 = __float2bfloat16(v.y);
    __nv_bfloat16 h2 = __float2bfloat16(v.z);
    __nv_bfloat16 h3 = __float2bfloat16(v.w);
    __nv_bfloat16 l0 = __float2bfloat16(v.x - __bfloat162float(h0));
    __nv_bfloat16 l1 = __float2bfloat16(v.y - __bfloat162float(h1));
    __nv_bfloat16 l2 = __float2bfloat16(v.z - __bfloat162float(h2));
    __nv_bfloat16 l3 = __float2bfloat16(v.w - __bfloat162float(h3));
    *(__nv_bfloat162*)(hi_base + half_off * 2)     = __halves2bfloat162(h0, h1);
    *(__nv_bfloat162*)(hi_base + half_off * 2 + 4) = __halves2bfloat162(h2, h3);
    *(__nv_bfloat162*)(lo_base + half_off * 2)     = __halves2bfloat162(l0, l1);
    *(__nv_bfloat162*)(lo_base + half_off * 2 + 4) = __halves2bfloat162(l2, l3);
}

__device__ __forceinline__ void mma_bf16(float* c, const uint32_t* a, const uint32_t* b) {
    asm volatile(
        "mma.sync.aligned.m16n8k16.row.col.f32.bf16.bf16.f32 "
        "{%0,%1,%2,%3}, {%4,%5,%6,%7}, {%8,%9}, {%0,%1,%2,%3};"
        : "+f"(c[0]), "+f"(c[1]), "+f"(c[2]), "+f"(c[3])
        : "r"(a[0]), "r"(a[1]), "r"(a[2]), "r"(a[3]), "r"(b[0]), "r"(b[1]));
}

__global__ void __launch_bounds__(256, 1)
k_gemm_mma(const float* __restrict__ x, const float* __restrict__ W,
           const float* __restrict__ bias, float* __restrict__ out) {
    extern __shared__ char smem[];
    __nv_bfloat16* sWhi = (__nv_bfloat16*)(smem + OFF_WHI);
    __nv_bfloat16* sWlo = (__nv_bfloat16*)(smem + OFF_WLO);
    __nv_bfloat16* sAhi = (__nv_bfloat16*)(smem + OFF_AHI);
    __nv_bfloat16* sAlo = (__nv_bfloat16*)(smem + OFF_ALO);
    float* sB  = (float*)(smem + OFF_BIAS);
    float* sSO = (float*)(smem + OFF_SO);
    float* sMM = (float*)(smem + OFF_MM);

    int tid = threadIdx.x, wid = tid >> 5, lane = tid & 31;
    int n0 = blockIdx.x * 128;

    if (tid < 128) {
        sB[tid] = bias[tid];
        int n = n0 + tid;
        if (n >= N_NODES) n = 0;
        float dout = (float)(g_deg_out[n] + 1);
        float din  = (float)(g_deg_in[n] + 1);
        sSO[tid] = rsqrtf(dout);
        sMM[tid] = rsqrtf(din) / dout;
    }

    // --- W conversion: [128 N][256 K] f32 -> split bf16, padded rows ---
    for (int idx = tid; idx < 8192; idx += 256) {
        int j = idx >> 6;            // N row
        int k = (idx & 63) * 4;      // k base
        float4 w = ((const float4*)W)[idx];
        split_store4((char*)sWhi, (char*)sWlo, j * W_PITCH + k, w);
    }
    // --- A half0 conversion: pure x rows ---
    for (int idx = tid; idx < 4096; idx += 256) {
        int row = idx >> 5;
        int k   = (idx & 31) * 4;
        int n   = n0 + row;
        if (n >= N_NODES) n = 0;
        float4 v = ((const float4*)(x + (size_t)n * D))[idx & 31];
        split_store4((char*)sAhi, (char*)sAlo, row * A_PITCH + k, v);
    }
    __syncthreads();

    // warp tiling: 2 (M) x 4 (N); warp tile 64M x 32N
    int wm = (wid & 1) * 64;         // warp M base
    int wn = (wid >> 1) * 32;        // warp N base
    int lg = lane >> 2;              // group 0..7
    int lk = (lane & 3) * 2;         // k/col pair offset

    float acc[4][4][4];
    #pragma unroll
    for (int mi = 0; mi < 4; mi++)
        #pragma unroll
        for (int ni = 0; ni < 4; ni++)
            #pragma unroll
            for (int q = 0; q < 4; q++) acc[mi][ni][q] = 0.0f;

    #pragma unroll
    for (int h = 0; h < 2; h++) {
        if (h == 1) {
            __syncthreads();   // all warps done reading half0 A
            // --- A half1: a = (agg + x*so) * m ---
            for (int idx = tid; idx < 4096; idx += 256) {
                int row = idx >> 5;
                int q   = idx & 31;
                int k   = q * 4;
                int n   = n0 + row;
                if (n >= N_NODES) n = 0;
                float4 a  = ((const float4*)(g_agg + (size_t)n * D))[q];
                float4 xv = ((const float4*)(x + (size_t)n * D))[q];
                float so = sSO[row], m = sMM[row];
                float4 v;
                v.x = (a.x + xv.x * so) * m;
                v.y = (a.y + xv.y * so) * m;
                v.z = (a.z + xv.z * so) * m;
                v.w = (a.w + xv.w * so) * m;
                split_store4((char*)sAhi, (char*)sAlo, row * A_PITCH + k, v);
            }
            __syncthreads();
        }
        for (int ks = 0; ks < 8; ks++) {
            int kb = ks * 16;            // k base within half (A)
            int kg = h * 128 + kb;       // global k (W)
            // B frags for 4 n-tiles (hi + lo)
            uint32_t bh[4][2], bl[4][2];
            #pragma unroll
            for (int ni = 0; ni < 4; ni++) {
                int nrow = wn + ni * 8 + lg;
                const __nv_bfloat16* ph = sWhi + nrow * W_PITCH + kg + lk;
                const __nv_bfloat16* pl = sWlo + nrow * W_PITCH + kg + lk;
                bh[ni][0] = *(const uint32_t*)(ph);
                bh[ni][1] = *(const uint32_t*)(ph + 8);
                bl[ni][0] = *(const uint32_t*)(pl);
                bl[ni][1] = *(const uint32_t*)(pl + 8);
            }
            #pragma unroll
            for (int mi = 0; mi < 4; mi++) {
                int mrow = wm + mi * 16 + lg;
                const __nv_bfloat16* ph = sAhi + mrow * A_PITCH + kb + lk;
                const __nv_bfloat16* pl = sAlo + mrow * A_PITCH + kb + lk;
                uint32_t ah[4], al[4];
                ah[0] = *(const uint32_t*)(ph);
                ah[1] = *(const uint32_t*)(ph + 8 * A_PITCH);
                ah[2] = *(const uint32_t*)(ph + 8);
                ah[3] = *(const uint32_t*)(ph + 8 * A_PITCH + 8);
                al[0] = *(const uint32_t*)(pl);
                al[1] = *(const uint32_t*)(pl + 8 * A_PITCH);
                al[2] = *(const uint32_t*)(pl + 8);
                al[3] = *(const uint32_t*)(pl + 8 * A_PITCH + 8);
                #pragma unroll
                for (int ni = 0; ni < 4; ni++) {
                    mma_bf16(acc[mi][ni], ah, bh[ni]);
                    mma_bf16(acc[mi][ni], ah, bl[ni]);
                    mma_bf16(acc[mi][ni], al, bh[ni]);
                }
            }
        }
    }

    // --- epilogue: acc -> out (+bias) ---
    #pragma unroll
    for (int mi = 0; mi < 4; mi++) {
        int r0 = n0 + wm + mi * 16 + lg;
        int r1 = r0 + 8;
        #pragma unroll
        for (int ni = 0; ni < 4; ni++) {
            int col = wn + ni * 8 + lk;
            float b0 = sB[col], b1 = sB[col + 1];
            if (r0 < N_NODES) {
                float2 v = {acc[mi][ni][0] + b0, acc[mi][ni][1] + b1};
                *(float2*)(out + (size_t)r0 * D + col) = v;
            }
            if (r1 < N_NODES) {
                float2 v = {acc[mi][ni][2] + b0, acc[mi][ni][3] + b1};
                *(float2*)(out + (size_t)r1 * D + col) = v;
            }
        }
    }
}

// ---------------- launch ----------------
extern "C" void kernel_launch(void* const* d_in, const int* in_sizes, int n_in,
                              void* d_out, int out_size) {
    const float* x   = (const float*)d_in[0];
    const void*  snd = d_in[1];
    const void*  rcv = d_in[2];
    const float* W   = nullptr;
    const float* b   = nullptr;
    for (int i = 3; i < n_in; i++) {
        if (in_sizes[i] == 2 * D * D) W = (const float*)d_in[i];
        else if (in_sizes[i] == D)    b = (const float*)d_in[i];
    }
    float* out = (float*)d_out;

    k_init<<<(N_NODES * D + 255) / 256, 256>>>(snd);
    k_deg<<<(N_EDGES + 255) / 256, 256>>>(snd, rcv);
    k_scatter<<<N_EDGES / 8, 256>>>(x, snd, rcv);

    cudaFuncSetAttribute(k_gemm_mma, cudaFuncAttributeMaxDynamicSharedMemorySize, SMEM_K3);
    k_gemm_mma<<<(N_NODES + 127) / 128, 256, SMEM_K3>>>(x, W, b, out);
}

// round 5
// speedup vs baseline: 1.9871x; 1.1103x over previous
#include <cuda_runtime.h>
#include <cuda_bf16.h>
#include <stdint.h>

#define N_NODES 50000
#define N_EDGES 625000
#define D 128

// ---------------- scratch (no allocs allowed) ----------------
__device__ int   g_deg_out[N_NODES];
__device__ int   g_deg_in[N_NODES];
__device__ float g_agg[(size_t)N_NODES * D];      // 25.6 MB, L2-resident
__device__ int   g_is64;
__device__ __nv_bfloat16 g_Whi[128 * 256];        // W split hi (row-major [N][K])
__device__ __nv_bfloat16 g_Wlo[128 * 256];        // W split lo

// ---------------- helpers ----------------
__device__ __forceinline__ uint32_t smem_u32(const void* p) {
    uint32_t a;
    asm("{ .reg .u64 t; cvta.to.shared.u64 t, %1; cvt.u32.u64 %0, t; }" : "=r"(a) : "l"(p));
    return a;
}
__device__ __forceinline__ void ldsm_x4(uint32_t* r, uint32_t addr) {
    asm volatile("ldmatrix.sync.aligned.m8n8.x4.shared.b16 {%0,%1,%2,%3}, [%4];"
                 : "=r"(r[0]), "=r"(r[1]), "=r"(r[2]), "=r"(r[3]) : "r"(addr));
}
__device__ __forceinline__ void cp16(uint32_t dst, const void* src) {
    asm volatile("cp.async.cg.shared.global [%0], [%1], 16;" :: "r"(dst), "l"(src));
}
__device__ __forceinline__ void mma_bf16(float* c, const uint32_t* a, const uint32_t* b) {
    asm volatile(
        "mma.sync.aligned.m16n8k16.row.col.f32.bf16.bf16.f32 "
        "{%0,%1,%2,%3}, {%4,%5,%6,%7}, {%8,%9}, {%0,%1,%2,%3};"
        : "+f"(c[0]), "+f"(c[1]), "+f"(c[2]), "+f"(c[3])
        : "r"(a[0]), "r"(a[1]), "r"(a[2]), "r"(a[3]), "r"(b[0]), "r"(b[1]));
}

__device__ __forceinline__ int load_idx(const void* p, int e, int is64) {
    return is64 ? (int)((const long long*)p)[e] : ((const int*)p)[e];
}

// ---------------- K0: dtype probe (zeroing moved to cudaMemsetAsync) ----------------
__global__ void k_probe(const void* __restrict__ senders) {
    if (threadIdx.x == 0) {
        const int* w = (const int*)senders;
        int is64 = 1;
        #pragma unroll
        for (int k = 0; k < 16; k++) if (w[2 * k + 1] != 0) is64 = 0;
        g_is64 = is64;
    }
}

// ---------------- K0b: W -> split bf16 (runs once per launch, ~2us) ----------------
__global__ void k_wconv(const float* __restrict__ W) {
    int i = blockIdx.x * blockDim.x + threadIdx.x;
    if (i >= 128 * 256) return;
    float v = W[i];
    __nv_bfloat16 h = __float2bfloat16(v);
    g_Whi[i] = h;
    g_Wlo[i] = __float2bfloat16(v - __bfloat162float(h));
}

// ---------------- K1: degree histograms ----------------
__global__ void k_deg(const void* __restrict__ senders, const void* __restrict__ receivers) {
    int e = blockIdx.x * blockDim.x + threadIdx.x;
    if (e >= N_EDGES) return;
    int is64 = g_is64;
    int s = load_idx(senders, e, is64);
    int r = load_idx(receivers, e, is64);
    atomicAdd(&g_deg_in[s], 1);
    atomicAdd(&g_deg_out[r], 1);
}

// ---------------- K2: edge scatter (1 warp per edge, v4 reductions) ----------------
__global__ void __launch_bounds__(256) k_scatter(const float* __restrict__ x,
                                                 const void* __restrict__ senders,
                                                 const void* __restrict__ receivers) {
    int warp = (blockIdx.x * blockDim.x + threadIdx.x) >> 5;
    int lane = threadIdx.x & 31;
    if (warp >= N_EDGES) return;
    int is64 = g_is64;
    int s = load_idx(senders, warp, is64);
    int r = load_idx(receivers, warp, is64);
    float scale = rsqrtf((float)(g_deg_out[s] + 1));
    float4 v = ((const float4*)(x + (size_t)s * D))[lane];
    v.x *= scale; v.y *= scale; v.z *= scale; v.w *= scale;
    float* dst = g_agg + (size_t)r * D + lane * 4;
    asm volatile("red.global.add.v4.f32 [%0], {%1,%2,%3,%4};"
                 :: "l"(dst), "f"(v.x), "f"(v.y), "f"(v.z), "f"(v.w) : "memory");
}

// ---------------- K3: split-bf16 GEMM, 512 thr, ldmatrix + cp.async W ----------------
// out = [x | a] @ W^T + b ,  a = (agg + x*rsqrt(do)) * rsqrt(di)/do
// D = Ahi*Whi + Ahi*Wlo + Alo*Whi (f32 accum). CTA: M=128,N=128,K=256 (2 halves).
#define A_PITCH 136            // halves (272B row; 272 % 128 = 16B -> LDSM conflict-free)
#define W_PITCH 264            // halves (528B row)
#define OFF_WHI  0
#define OFF_WLO  (OFF_WHI + 128 * W_PITCH * 2)
#define OFF_AHI  (OFF_WLO + 128 * W_PITCH * 2)
#define OFF_ALO  (OFF_AHI + 128 * A_PITCH * 2)
#define OFF_BIAS (OFF_ALO + 128 * A_PITCH * 2)
#define OFF_SO   (OFF_BIAS + 512)
#define OFF_MM   (OFF_SO + 512)
#define SMEM_K3  (OFF_MM + 512)          // 206336 bytes

__device__ __forceinline__ void split_store4(char* hi_base, char* lo_base, int half_off, float4 v) {
    __nv_bfloat16 h0 = __float2bfloat16(v.x);
    __nv_bfloat16 h1 = __float2bfloat16(v.y);
    __nv_bfloat16 h2 = __float2bfloat16(v.z);
    __nv_bfloat16 h3 = __float2bfloat16(v.w);
    __nv_bfloat16 l0 = __float2bfloat16(v.x - __bfloat162float(h0));
    __nv_bfloat16 l1 = __float2bfloat16(v.y - __bfloat162float(h1));
    __nv_bfloat16 l2 = __float2bfloat16(v.z - __bfloat162float(h2));
    __nv_bfloat16 l3 = __float2bfloat16(v.w - __bfloat162float(h3));
    *(__nv_bfloat162*)(hi_base + half_off * 2)     = __halves2bfloat162(h0, h1);
    *(__nv_bfloat162*)(hi_base + half_off * 2 + 4) = __halves2bfloat162(h2, h3);
    *(__nv_bfloat162*)(lo_base + half_off * 2)     = __halves2bfloat162(l0, l1);
    *(__nv_bfloat162*)(lo_base + half_off * 2 + 4) = __halves2bfloat162(l2, l3);
}

__global__ void __launch_bounds__(512, 1)
k_gemm_mma(const float* __restrict__ x, const float* __restrict__ bias,
           float* __restrict__ out) {
    extern __shared__ char smem[];
    __nv_bfloat16* sAhi = (__nv_bfloat16*)(smem + OFF_AHI);
    __nv_bfloat16* sAlo = (__nv_bfloat16*)(smem + OFF_ALO);
    float* sB  = (float*)(smem + OFF_BIAS);
    float* sSO = (float*)(smem + OFF_SO);
    float* sMM = (float*)(smem + OFF_MM);

    int tid = threadIdx.x, wid = tid >> 5, lane = tid & 31;
    int n0 = blockIdx.x * 128;

    // --- W fill: straight bf16 copy via cp.async (overlaps A conversion) ---
    uint32_t sWhiA = smem_u32(smem + OFF_WHI);
    uint32_t sWloA = smem_u32(smem + OFF_WLO);
    for (int idx = tid; idx < 4096; idx += 512) {        // 128 rows x 32 chunks of 8 halves
        int row = idx >> 5;
        int c   = (idx & 31) * 8;
        cp16(sWhiA + (row * W_PITCH + c) * 2, g_Whi + row * 256 + c);
        cp16(sWloA + (row * W_PITCH + c) * 2, g_Wlo + row * 256 + c);
    }
    asm volatile("cp.async.commit_group;");

    if (tid < 128) {
        sB[tid] = bias[tid];
        int n = n0 + tid;
        if (n >= N_NODES) n = 0;
        float dout = (float)(g_deg_out[n] + 1);
        float din  = (float)(g_deg_in[n] + 1);
        sSO[tid] = rsqrtf(dout);
        sMM[tid] = rsqrtf(din) / dout;
    }

    // --- A half0 conversion: pure x rows ---
    for (int idx = tid; idx < 4096; idx += 512) {
        int row = idx >> 5;
        int k   = (idx & 31) * 4;
        int n   = n0 + row;
        if (n >= N_NODES) n = 0;
        float4 v = ((const float4*)(x + (size_t)n * D))[idx & 31];
        split_store4((char*)sAhi, (char*)sAlo, row * A_PITCH + k, v);
    }
    asm volatile("cp.async.wait_group 0;");
    __syncthreads();

    // warp tiling: 4 (M) x 4 (N); warp tile 32M x 32N
    int wm = (wid & 3) * 32;
    int wn = (wid >> 2) * 32;

    // per-lane ldmatrix source offsets (halves)
    int aRow = lane & 15;
    int aCol = (lane >> 4) * 8;
    int bRow = (lane & 7) | ((lane >> 1) & 8);
    int bCol = lane & 8;
    uint32_t aAhi = smem_u32(sAhi) + (uint32_t)(((wm + aRow) * A_PITCH + aCol) * 2);
    uint32_t aAlo = smem_u32(sAlo) + (uint32_t)(((wm + aRow) * A_PITCH + aCol) * 2);
    uint32_t aBhi = sWhiA + (uint32_t)(((wn + bRow) * W_PITCH + bCol) * 2);
    uint32_t aBlo = sWloA + (uint32_t)(((wn + bRow) * W_PITCH + bCol) * 2);

    float acc[2][4][4];
    #pragma unroll
    for (int mi = 0; mi < 2; mi++)
        #pragma unroll
        for (int ni = 0; ni < 4; ni++)
            #pragma unroll
            for (int q = 0; q < 4; q++) acc[mi][ni][q] = 0.0f;

    #pragma unroll
    for (int h = 0; h < 2; h++) {
        if (h == 1) {
            __syncthreads();   // all warps done reading half0 A
            for (int idx = tid; idx < 4096; idx += 512) {
                int row = idx >> 5;
                int q   = idx & 31;
                int k   = q * 4;
                int n   = n0 + row;
                if (n >= N_NODES) n = 0;
                float4 a  = ((const float4*)(g_agg + (size_t)n * D))[q];
                float4 xv = ((const float4*)(x + (size_t)n * D))[q];
                float so = sSO[row], m = sMM[row];
                float4 v;
                v.x = (a.x + xv.x * so) * m;
                v.y = (a.y + xv.y * so) * m;
                v.z = (a.z + xv.z * so) * m;
                v.w = (a.w + xv.w * so) * m;
                split_store4((char*)sAhi, (char*)sAlo, row * A_PITCH + k, v);
            }
            __syncthreads();
        }
        #pragma unroll
        for (int ks = 0; ks < 8; ks++) {
            int kb = ks * 16;                  // k in A half
            int kg = h * 128 + kb;             // k in W
            uint32_t bh[2][4], bl[2][4];       // [nip][4 regs] = b0/b1 of ni=2nip, 2nip+1
            #pragma unroll
            for (int nip = 0; nip < 2; nip++) {
                uint32_t off = (uint32_t)((nip * 16 * W_PITCH + kg) * 2);
                ldsm_x4(bh[nip], aBhi + off);
                ldsm_x4(bl[nip], aBlo + off);
            }
            #pragma unroll
            for (int mi = 0; mi < 2; mi++) {
                uint32_t off = (uint32_t)((mi * 16 * A_PITCH + kb) * 2);
                uint32_t ah[4], al[4];
                ldsm_x4(ah, aAhi + off);
                ldsm_x4(al, aAlo + off);
                #pragma unroll
                for (int ni = 0; ni < 4; ni++) {
                    const uint32_t* b_hi = &bh[ni >> 1][(ni & 1) * 2];
                    const uint32_t* b_lo = &bl[ni >> 1][(ni & 1) * 2];
                    mma_bf16(acc[mi][ni], ah, b_hi);
                    mma_bf16(acc[mi][ni], ah, b_lo);
                    mma_bf16(acc[mi][ni], al, b_hi);
                }
            }
        }
    }

    // --- epilogue ---
    int lg = lane >> 2;
    int lk = (lane & 3) * 2;
    #pragma unroll
    for (int mi = 0; mi < 2; mi++) {
        int r0 = n0 + wm + mi * 16 + lg;
        int r1 = r0 + 8;
        #pragma unroll
        for (int ni = 0; ni < 4; ni++) {
            int col = wn + ni * 8 + lk;
            float b0 = sB[col], b1 = sB[col + 1];
            if (r0 < N_NODES) {
                float2 v = {acc[mi][ni][0] + b0, acc[mi][ni][1] + b1};
                *(float2*)(out + (size_t)r0 * D + col) = v;
            }
            if (r1 < N_NODES) {
                float2 v = {acc[mi][ni][2] + b0, acc[mi][ni][3] + b1};
                *(float2*)(out + (size_t)r1 * D + col) = v;
            }
        }
    }
}

// ---------------- launch ----------------
extern "C" void kernel_launch(void* const* d_in, const int* in_sizes, int n_in,
                              void* d_out, int out_size) {
    const float* x   = (const float*)d_in[0];
    const void*  snd = d_in[1];
    const void*  rcv = d_in[2];
    const float* W   = nullptr;
    const float* b   = nullptr;
    for (int i = 3; i < n_in; i++) {
        if (in_sizes[i] == 2 * D * D) W = (const float*)d_in[i];
        else if (in_sizes[i] == D)    b = (const float*)d_in[i];
    }
    float* out = (float*)d_out;

    // HW memset path for scratch zeroing (graph-capturable, no allocs)
    void *p_agg = nullptr, *p_do = nullptr, *p_di = nullptr;
    cudaGetSymbolAddress(&p_agg, g_agg);
    cudaGetSymbolAddress(&p_do,  g_deg_out);
    cudaGetSymbolAddress(&p_di,  g_deg_in);
    cudaMemsetAsync(p_agg, 0, sizeof(float) * (size_t)N_NODES * D);
    cudaMemsetAsync(p_do,  0, sizeof(int) * N_NODES);
    cudaMemsetAsync(p_di,  0, sizeof(int) * N_NODES);

    k_probe<<<1, 32>>>(snd);
    k_wconv<<<128, 256>>>(W);
    k_deg<<<(N_EDGES + 255) / 256, 256>>>(snd, rcv);
    k_scatter<<<N_EDGES / 8, 256>>>(x, snd, rcv);

    cudaFuncSetAttribute(k_gemm_mma, cudaFuncAttributeMaxDynamicSharedMemorySize, SMEM_K3);
    k_gemm_mma<<<(N_NODES + 127) / 128, 512, SMEM_K3>>>(x, b, out);
}

// round 7
// speedup vs baseline: 2.4949x; 1.2556x over previous
#include <cuda_runtime.h>
#include <cuda_bf16.h>
#include <stdint.h>

#define N_NODES 50000
#define N_EDGES 625000
#define D 128
#define NPART 391                      // ceil(N_NODES/128)

// ---------------- scratch (no allocs allowed) ----------------
__device__ int   g_deg_out[N_NODES];   // receiver histogram
__device__ int   g_deg_in[N_NODES];    // sender histogram
__device__ float g_agg[(size_t)N_NODES * D];   // final scaled aggregate a[n]
__device__ int   g_is64;
__device__ __nv_bfloat16 g_Whi[128 * 256];
__device__ __nv_bfloat16 g_Wlo[128 * 256];
__device__ int   g_off[N_NODES + 1];
__device__ int   g_cursor[N_NODES];
__device__ int   g_csr[N_EDGES];       // sender ids bucketed by receiver
__device__ float g_sscale[N_NODES];    // rsqrt(deg_out+1)
__device__ float g_mscale[N_NODES];    // rsqrt(deg_in+1)/(deg_out+1)
__device__ int   g_part[NPART];
__device__ int   g_pbase[NPART];

// ---------------- helpers ----------------
__device__ __forceinline__ uint32_t smem_u32(const void* p) {
    uint32_t a;
    asm("{ .reg .u64 t; cvta.to.shared.u64 t, %1; cvt.u32.u64 %0, t; }" : "=r"(a) : "l"(p));
    return a;
}
__device__ __forceinline__ void ldsm_x4(uint32_t* r, uint32_t addr) {
    asm volatile("ldmatrix.sync.aligned.m8n8.x4.shared.b16 {%0,%1,%2,%3}, [%4];"
                 : "=r"(r[0]), "=r"(r[1]), "=r"(r[2]), "=r"(r[3]) : "r"(addr));
}
__device__ __forceinline__ void cp16(uint32_t dst, const void* src) {
    asm volatile("cp.async.cg.shared.global [%0], [%1], 16;" :: "r"(dst), "l"(src));
}
__device__ __forceinline__ void mma_bf16(float* c, const uint32_t* a, const uint32_t* b) {
    asm volatile(
        "mma.sync.aligned.m16n8k16.row.col.f32.bf16.bf16.f32 "
        "{%0,%1,%2,%3}, {%4,%5,%6,%7}, {%8,%9}, {%0,%1,%2,%3};"
        : "+f"(c[0]), "+f"(c[1]), "+f"(c[2]), "+f"(c[3])
        : "r"(a[0]), "r"(a[1]), "r"(a[2]), "r"(a[3]), "r"(b[0]), "r"(b[1]));
}
__device__ __forceinline__ int load_idx(const void* p, int e, int is64) {
    return is64 ? (int)((const long long*)p)[e] : ((const int*)p)[e];
}

// ---------------- K0: dtype probe ----------------
__global__ void k_probe(const void* __restrict__ senders) {
    if (threadIdx.x == 0) {
        const int* w = (const int*)senders;
        int is64 = 1;
        #pragma unroll
        for (int k = 0; k < 16; k++) if (w[2 * k + 1] != 0) is64 = 0;
        g_is64 = is64;
    }
}

// ---------------- K0b: W -> split bf16 ----------------
__global__ void k_wconv(const float* __restrict__ W) {
    int i = blockIdx.x * blockDim.x + threadIdx.x;
    if (i >= 128 * 256) return;
    float v = W[i];
    __nv_bfloat16 h = __float2bfloat16(v);
    g_Whi[i] = h;
    g_Wlo[i] = __float2bfloat16(v - __bfloat162float(h));
}

// ---------------- K1: degree histograms ----------------
__global__ void k_deg(const void* __restrict__ senders, const void* __restrict__ receivers) {
    int e = blockIdx.x * blockDim.x + threadIdx.x;
    if (e >= N_EDGES) return;
    int is64 = g_is64;
    int s = load_idx(senders, e, is64);
    int r = load_idx(receivers, e, is64);
    atomicAdd(&g_deg_in[s], 1);
    atomicAdd(&g_deg_out[r], 1);
}

// ---------------- scan: 3-kernel exclusive scan of g_deg_out ----------------
__global__ void k_scan1() {              // NPART blocks x 128
    __shared__ int sd[128];
    int tid = threadIdx.x;
    int i = blockIdx.x * 128 + tid;
    int v = (i < N_NODES) ? g_deg_out[i] : 0;
    sd[tid] = v; __syncthreads();
    #pragma unroll
    for (int s = 64; s > 0; s >>= 1) {
        if (tid < s) sd[tid] += sd[tid + s];
        __syncthreads();
    }
    if (tid == 0) g_part[blockIdx.x] = sd[0];
}
__global__ void k_scan2() {              // 1 block x 512
    __shared__ int sd[512];
    int tid = threadIdx.x;
    int v = (tid < NPART) ? g_part[tid] : 0;
    sd[tid] = v; __syncthreads();
    for (int off = 1; off < 512; off <<= 1) {
        int t = (tid >= off) ? sd[tid - off] : 0;
        __syncthreads();
        sd[tid] += t;
        __syncthreads();
    }
    if (tid < NPART) g_pbase[tid] = sd[tid] - v;   // exclusive
}
__global__ void k_scan3() {              // NPART blocks x 128: offsets + scales + cursor
    __shared__ int sd[128];
    int tid = threadIdx.x;
    int i = blockIdx.x * 128 + tid;
    int v = (i < N_NODES) ? g_deg_out[i] : 0;
    sd[tid] = v; __syncthreads();
    for (int off = 1; off < 128; off <<= 1) {
        int t = (tid >= off) ? sd[tid - off] : 0;
        __syncthreads();
        sd[tid] += t;
        __syncthreads();
    }
    int exc = g_pbase[blockIdx.x] + sd[tid] - v;
    if (i < N_NODES) {
        g_off[i] = exc;
        g_cursor[i] = exc;
        float dout = (float)(v + 1);
        float din  = (float)(g_deg_in[i] + 1);
        g_sscale[i] = rsqrtf(dout);
        g_mscale[i] = rsqrtf(din) / dout;
        if (i == N_NODES - 1) g_off[N_NODES] = exc + v;
    }
}

// ---------------- K2a: bucket fill ----------------
__global__ void k_fill(const void* __restrict__ senders, const void* __restrict__ receivers) {
    int e = blockIdx.x * blockDim.x + threadIdx.x;
    if (e >= N_EDGES) return;
    int is64 = g_is64;
    int s = load_idx(senders, e, is64);
    int r = load_idx(receivers, e, is64);
    int pos = atomicAdd(&g_cursor[r], 1);
    g_csr[pos] = s;
}

// ---------------- K2b: gather (1 warp per node) ----------------
__global__ void __launch_bounds__(256) k_gather(const float* __restrict__ x) {
    int w = (blockIdx.x * blockDim.x + threadIdx.x) >> 5;
    int lane = threadIdx.x & 31;
    if (w >= N_NODES) return;
    int beg = g_off[w], end = g_off[w + 1];

    // self-loop term
    float ss = g_sscale[w];
    float4 acc = ((const float4*)(x + (size_t)w * D))[lane];
    acc.x *= ss; acc.y *= ss; acc.z *= ss; acc.w *= ss;
    float4 acc2 = {0.f, 0.f, 0.f, 0.f};

    int e = beg;
    for (; e + 1 < end; e += 2) {
        int s0 = g_csr[e], s1 = g_csr[e + 1];
        float c0 = g_sscale[s0], c1 = g_sscale[s1];
        float4 v0 = ((const float4*)(x + (size_t)s0 * D))[lane];
        float4 v1 = ((const float4*)(x + (size_t)s1 * D))[lane];
        acc.x  += v0.x * c0; acc.y  += v0.y * c0; acc.z  += v0.z * c0; acc.w  += v0.w * c0;
        acc2.x += v1.x * c1; acc2.y += v1.y * c1; acc2.z += v1.z * c1; acc2.w += v1.w * c1;
    }
    if (e < end) {
        int s0 = g_csr[e];
        float c0 = g_sscale[s0];
        float4 v0 = ((const float4*)(x + (size_t)s0 * D))[lane];
        acc.x += v0.x * c0; acc.y += v0.y * c0; acc.z += v0.z * c0; acc.w += v0.w * c0;
    }
    float m = g_mscale[w];
    float4 r;
    r.x = (acc.x + acc2.x) * m;
    r.y = (acc.y + acc2.y) * m;
    r.z = (acc.z + acc2.z) * m;
    r.w = (acc.w + acc2.w) * m;
    ((float4*)(g_agg + (size_t)w * D))[lane] = r;
}

// ---------------- K3: split-bf16 GEMM (512 thr, ldmatrix, cp.async W) ----------------
#define A_PITCH 136
#define W_PITCH 264
#define OFF_WHI  0
#define OFF_WLO  (OFF_WHI + 128 * W_PITCH * 2)
#define OFF_AHI  (OFF_WLO + 128 * W_PITCH * 2)
#define OFF_ALO  (OFF_AHI + 128 * A_PITCH * 2)
#define OFF_BIAS (OFF_ALO + 128 * A_PITCH * 2)
#define SMEM_K3  (OFF_BIAS + 512)

__device__ __forceinline__ void split_store4(char* hi_base, char* lo_base, int half_off, float4 v) {
    __nv_bfloat16 h0 = __float2bfloat16(v.x);
    __nv_bfloat16 h1 = __float2bfloat16(v.y);
    __nv_bfloat16 h2 = __float2bfloat16(v.z);
    __nv_bfloat16 h3 = __float2bfloat16(v.w);
    __nv_bfloat16 l0 = __float2bfloat16(v.x - __bfloat162float(h0));
    __nv_bfloat16 l1 = __float2bfloat16(v.y - __bfloat162float(h1));
    __nv_bfloat16 l2 = __float2bfloat16(v.z - __bfloat162float(h2));
    __nv_bfloat16 l3 = __float2bfloat16(v.w - __bfloat162float(h3));
    *(__nv_bfloat162*)(hi_base + half_off * 2)     = __halves2bfloat162(h0, h1);
    *(__nv_bfloat162*)(hi_base + half_off * 2 + 4) = __halves2bfloat162(h2, h3);
    *(__nv_bfloat162*)(lo_base + half_off * 2)     = __halves2bfloat162(l0, l1);
    *(__nv_bfloat162*)(lo_base + half_off * 2 + 4) = __halves2bfloat162(l2, l3);
}

__global__ void __launch_bounds__(512, 1)
k_gemm_mma(const float* __restrict__ x, const float* __restrict__ bias,
           float* __restrict__ out) {
    extern __shared__ char smem[];
    __nv_bfloat16* sAhi = (__nv_bfloat16*)(smem + OFF_AHI);
    __nv_bfloat16* sAlo = (__nv_bfloat16*)(smem + OFF_ALO);
    float* sB = (float*)(smem + OFF_BIAS);

    int tid = threadIdx.x, wid = tid >> 5, lane = tid & 31;
    int n0 = blockIdx.x * 128;

    uint32_t sWhiA = smem_u32(smem + OFF_WHI);
    uint32_t sWloA = smem_u32(smem + OFF_WLO);
    for (int idx = tid; idx < 4096; idx += 512) {
        int row = idx >> 5;
        int c   = (idx & 31) * 8;
        cp16(sWhiA + (row * W_PITCH + c) * 2, g_Whi + row * 256 + c);
        cp16(sWloA + (row * W_PITCH + c) * 2, g_Wlo + row * 256 + c);
    }
    asm volatile("cp.async.commit_group;");

    if (tid < 128) sB[tid] = bias[tid];

    // A half0: x rows
    for (int idx = tid; idx < 4096; idx += 512) {
        int row = idx >> 5;
        int k   = (idx & 31) * 4;
        int n   = n0 + row;
        if (n >= N_NODES) n = 0;
        float4 v = ((const float4*)(x + (size_t)n * D))[idx & 31];
        split_store4((char*)sAhi, (char*)sAlo, row * A_PITCH + k, v);
    }
    asm volatile("cp.async.wait_group 0;");
    __syncthreads();

    int wm = (wid & 3) * 32;
    int wn = (wid >> 2) * 32;
    int aRow = lane & 15;
    int aCol = (lane >> 4) * 8;
    int bRow = (lane & 7) | ((lane >> 1) & 8);
    int bCol = lane & 8;
    uint32_t aAhi = smem_u32(sAhi) + (uint32_t)(((wm + aRow) * A_PITCH + aCol) * 2);
    uint32_t aAlo = smem_u32(sAlo) + (uint32_t)(((wm + aRow) * A_PITCH + aCol) * 2);
    uint32_t aBhi = sWhiA + (uint32_t)(((wn + bRow) * W_PITCH + bCol) * 2);
    uint32_t aBlo = sWloA + (uint32_t)(((wn + bRow) * W_PITCH + bCol) * 2);

    float acc[2][4][4];
    #pragma unroll
    for (int mi = 0; mi < 2; mi++)
        #pragma unroll
        for (int ni = 0; ni < 4; ni++)
            #pragma unroll
            for (int q = 0; q < 4; q++) acc[mi][ni][q] = 0.0f;

    #pragma unroll
    for (int h = 0; h < 2; h++) {
        if (h == 1) {
            __syncthreads();
            // A half1: precomputed aggregate (already scaled)
            for (int idx = tid; idx < 4096; idx += 512) {
                int row = idx >> 5;
                int q   = idx & 31;
                int n   = n0 + row;
                if (n >= N_NODES) n = 0;
                float4 v = ((const float4*)(g_agg + (size_t)n * D))[q];
                split_store4((char*)sAhi, (char*)sAlo, row * A_PITCH + q * 4, v);
            }
            __syncthreads();
        }
        #pragma unroll
        for (int ks = 0; ks < 8; ks++) {
            int kb = ks * 16;
            int kg = h * 128 + kb;
            uint32_t bh[2][4], bl[2][4];
            #pragma unroll
            for (int nip = 0; nip < 2; nip++) {
                uint32_t off = (uint32_t)((nip * 16 * W_PITCH + kg) * 2);
                ldsm_x4(bh[nip], aBhi + off);
                ldsm_x4(bl[nip], aBlo + off);
            }
            #pragma unroll
            for (int mi = 0; mi < 2; mi++) {
                uint32_t off = (uint32_t)((mi * 16 * A_PITCH + kb) * 2);
                uint32_t ah[4], al[4];
                ldsm_x4(ah, aAhi + off);
                ldsm_x4(al, aAlo + off);
                #pragma unroll
                for (int ni = 0; ni < 4; ni++) {
                    const uint32_t* b_hi = &bh[ni >> 1][(ni & 1) * 2];
                    const uint32_t* b_lo = &bl[ni >> 1][(ni & 1) * 2];
                    mma_bf16(acc[mi][ni], ah, b_hi);
                    mma_bf16(acc[mi][ni], ah, b_lo);
                    mma_bf16(acc[mi][ni], al, b_hi);
                }
            }
        }
    }

    int lg = lane >> 2;
    int lk = (lane & 3) * 2;
    #pragma unroll
    for (int mi = 0; mi < 2; mi++) {
        int r0 = n0 + wm + mi * 16 + lg;
        int r1 = r0 + 8;
        #pragma unroll
        for (int ni = 0; ni < 4; ni++) {
            int col = wn + ni * 8 + lk;
            float b0 = sB[col], b1 = sB[col + 1];
            if (r0 < N_NODES) {
                float2 v = {acc[mi][ni][0] + b0, acc[mi][ni][1] + b1};
                *(float2*)(out + (size_t)r0 * D + col) = v;
            }
            if (r1 < N_NODES) {
                float2 v = {acc[mi][ni][2] + b0, acc[mi][ni][3] + b1};
                *(float2*)(out + (size_t)r1 * D + col) = v;
            }
        }
    }
}

// ---------------- launch ----------------
extern "C" void kernel_launch(void* const* d_in, const int* in_sizes, int n_in,
                              void* d_out, int out_size) {
    const float* x   = (const float*)d_in[0];
    const void*  snd = d_in[1];
    const void*  rcv = d_in[2];
    const float* W   = nullptr;
    const float* b   = nullptr;
    for (int i = 3; i < n_in; i++) {
        if (in_sizes[i] == 2 * D * D) W = (const float*)d_in[i];
        else if (in_sizes[i] == D)    b = (const float*)d_in[i];
    }
    float* out = (float*)d_out;

    void *p_do = nullptr, *p_di = nullptr;
    cudaGetSymbolAddress(&p_do, g_deg_out);
    cudaGetSymbolAddress(&p_di, g_deg_in);
    cudaMemsetAsync(p_do, 0, sizeof(int) * N_NODES);
    cudaMemsetAsync(p_di, 0, sizeof(int) * N_NODES);

    k_probe<<<1, 32>>>(snd);
    k_wconv<<<128, 256>>>(W);
    k_deg<<<(N_EDGES + 255) / 256, 256>>>(snd, rcv);
    k_scan1<<<NPART, 128>>>();
    k_scan2<<<1, 512>>>();
    k_scan3<<<NPART, 128>>>();
    k_fill<<<(N_EDGES + 255) / 256, 256>>>(snd, rcv);
    k_gather<<<(N_NODES * 32 + 255) / 256, 256>>>(x);

    cudaFuncSetAttribute(k_gemm_mma, cudaFuncAttributeMaxDynamicSharedMemorySize, SMEM_K3);
    k_gemm_mma<<<(N_NODES + 127) / 128, 512, SMEM_K3>>>(x, b, out);
}

// round 8
// speedup vs baseline: 2.4994x; 1.0018x over previous
#include <cuda_runtime.h>
#include <cuda_bf16.h>
#include <stdint.h>

#define N_NODES 50000
#define N_EDGES 625000
#define D 128
#define ELLCAP 64
#define MAXOVF 4096

// ---------------- scratch (no allocs allowed) ----------------
__device__ int   g_deg_out[N_NODES];   // receiver histogram (also ELL cursor)
__device__ int   g_deg_in[N_NODES];    // sender histogram
__device__ float g_agg[(size_t)N_NODES * D];   // raw aggregate (self + edges)
__device__ int   g_is64;
__device__ __nv_bfloat16 g_Whi[128 * 256];
__device__ __nv_bfloat16 g_Wlo[128 * 256];
__device__ int   g_ell[(size_t)N_NODES * ELLCAP];   // sender ids, bucketed by receiver
__device__ int   g_ovf_cnt;
__device__ int   g_ovf[2 * MAXOVF];
__device__ float g_sscale[N_NODES];    // rsqrt(deg_out+1)
__device__ float g_mscale[N_NODES];    // rsqrt(deg_in+1)/(deg_out+1)

// ---------------- helpers ----------------
__device__ __forceinline__ uint32_t smem_u32(const void* p) {
    uint32_t a;
    asm("{ .reg .u64 t; cvta.to.shared.u64 t, %1; cvt.u32.u64 %0, t; }" : "=r"(a) : "l"(p));
    return a;
}
__device__ __forceinline__ void ldsm_x4(uint32_t* r, uint32_t addr) {
    asm volatile("ldmatrix.sync.aligned.m8n8.x4.shared.b16 {%0,%1,%2,%3}, [%4];"
                 : "=r"(r[0]), "=r"(r[1]), "=r"(r[2]), "=r"(r[3]) : "r"(addr));
}
__device__ __forceinline__ void cp16(uint32_t dst, const void* src) {
    asm volatile("cp.async.cg.shared.global [%0], [%1], 16;" :: "r"(dst), "l"(src));
}
__device__ __forceinline__ void mma_bf16(float* c, const uint32_t* a, const uint32_t* b) {
    asm volatile(
        "mma.sync.aligned.m16n8k16.row.col.f32.bf16.bf16.f32 "
        "{%0,%1,%2,%3}, {%4,%5,%6,%7}, {%8,%9}, {%0,%1,%2,%3};"
        : "+f"(c[0]), "+f"(c[1]), "+f"(c[2]), "+f"(c[3])
        : "r"(a[0]), "r"(a[1]), "r"(a[2]), "r"(a[3]), "r"(b[0]), "r"(b[1]));
}
__device__ __forceinline__ int load_idx(const void* p, int e, int is64) {
    return is64 ? (int)((const long long*)p)[e] : ((const int*)p)[e];
}

// ---------------- K0: dtype probe ----------------
__global__ void k_probe(const void* __restrict__ senders) {
    if (threadIdx.x == 0) {
        const int* w = (const int*)senders;
        int is64 = 1;
        #pragma unroll
        for (int k = 0; k < 16; k++) if (w[2 * k + 1] != 0) is64 = 0;
        g_is64 = is64;
    }
}

// ---------------- K0b: W -> split bf16 ----------------
__global__ void k_wconv(const float* __restrict__ W) {
    int i = blockIdx.x * blockDim.x + threadIdx.x;
    if (i >= 128 * 256) return;
    float v = W[i];
    __nv_bfloat16 h = __float2bfloat16(v);
    g_Whi[i] = h;
    g_Wlo[i] = __float2bfloat16(v - __bfloat162float(h));
}

// ---------------- K1: fused degree count + ELL bucket fill ----------------
__global__ void k_ell(const void* __restrict__ senders, const void* __restrict__ receivers) {
    int e = blockIdx.x * blockDim.x + threadIdx.x;
    if (e >= N_EDGES) return;
    int is64 = g_is64;
    int s = load_idx(senders, e, is64);
    int r = load_idx(receivers, e, is64);
    atomicAdd(&g_deg_in[s], 1);
    int pos = atomicAdd(&g_deg_out[r], 1);       // histogram == cursor
    if (pos < ELLCAP) {
        g_ell[(size_t)r * ELLCAP + pos] = s;
    } else {
        int o = atomicAdd(&g_ovf_cnt, 1);
        if (o < MAXOVF) { g_ovf[2 * o] = r; g_ovf[2 * o + 1] = s; }
    }
}

// ---------------- K1b: per-node scales ----------------
__global__ void k_scale() {
    int i = blockIdx.x * blockDim.x + threadIdx.x;
    if (i >= N_NODES) return;
    float dout = (float)(g_deg_out[i] + 1);
    float din  = (float)(g_deg_in[i] + 1);
    g_sscale[i] = rsqrtf(dout);
    g_mscale[i] = rsqrtf(din) / dout;
}

// ---------------- K2: gather (1 warp per node, raw sums) ----------------
__global__ void __launch_bounds__(256) k_gather(const float* __restrict__ x) {
    int w = (blockIdx.x * blockDim.x + threadIdx.x) >> 5;
    int lane = threadIdx.x & 31;
    if (w >= N_NODES) return;
    int deg = g_deg_out[w];
    if (deg > ELLCAP) deg = ELLCAP;
    const int* row = g_ell + (size_t)w * ELLCAP;

    // self-loop term
    float ss = g_sscale[w];
    float4 acc = ((const float4*)(x + (size_t)w * D))[lane];
    acc.x *= ss; acc.y *= ss; acc.z *= ss; acc.w *= ss;
    float4 acc2 = {0.f, 0.f, 0.f, 0.f};

    int j = 0;
    for (; j + 1 < deg; j += 2) {
        int s0 = row[j], s1 = row[j + 1];
        float c0 = g_sscale[s0], c1 = g_sscale[s1];
        float4 v0 = ((const float4*)(x + (size_t)s0 * D))[lane];
        float4 v1 = ((const float4*)(x + (size_t)s1 * D))[lane];
        acc.x  += v0.x * c0; acc.y  += v0.y * c0; acc.z  += v0.z * c0; acc.w  += v0.w * c0;
        acc2.x += v1.x * c1; acc2.y += v1.y * c1; acc2.z += v1.z * c1; acc2.w += v1.w * c1;
    }
    if (j < deg) {
        int s0 = row[j];
        float c0 = g_sscale[s0];
        float4 v0 = ((const float4*)(x + (size_t)s0 * D))[lane];
        acc.x += v0.x * c0; acc.y += v0.y * c0; acc.z += v0.z * c0; acc.w += v0.w * c0;
    }
    float4 r;
    r.x = acc.x + acc2.x;
    r.y = acc.y + acc2.y;
    r.z = acc.z + acc2.z;
    r.w = acc.w + acc2.w;
    ((float4*)(g_agg + (size_t)w * D))[lane] = r;   // unscaled; m applied in GEMM
}

// ---------------- K2b: overflow fixup (normally 0 entries) ----------------
__global__ void __launch_bounds__(256) k_ovf(const float* __restrict__ x) {
    int warp = (blockIdx.x * blockDim.x + threadIdx.x) >> 5;
    int lane = threadIdx.x & 31;
    int cnt = g_ovf_cnt;
    if (cnt > MAXOVF) cnt = MAXOVF;
    for (int o = warp; o < cnt; o += (gridDim.x * blockDim.x) >> 5) {
        int r = g_ovf[2 * o], s = g_ovf[2 * o + 1];
        float c = g_sscale[s];
        float4 v = ((const float4*)(x + (size_t)s * D))[lane];
        v.x *= c; v.y *= c; v.z *= c; v.w *= c;
        float* dst = g_agg + (size_t)r * D + lane * 4;
        asm volatile("red.global.add.v4.f32 [%0], {%1,%2,%3,%4};"
                     :: "l"(dst), "f"(v.x), "f"(v.y), "f"(v.z), "f"(v.w) : "memory");
    }
}

// ---------------- K3: split-bf16 GEMM (512 thr, ldmatrix, cp.async W) ----------------
#define A_PITCH 136
#define W_PITCH 264
#define OFF_WHI  0
#define OFF_WLO  (OFF_WHI + 128 * W_PITCH * 2)
#define OFF_AHI  (OFF_WLO + 128 * W_PITCH * 2)
#define OFF_ALO  (OFF_AHI + 128 * A_PITCH * 2)
#define OFF_BIAS (OFF_ALO + 128 * A_PITCH * 2)
#define SMEM_K3  (OFF_BIAS + 512)

__device__ __forceinline__ void split_store4(char* hi_base, char* lo_base, int half_off, float4 v) {
    __nv_bfloat16 h0 = __float2bfloat16(v.x);
    __nv_bfloat16 h1 = __float2bfloat16(v.y);
    __nv_bfloat16 h2 = __float2bfloat16(v.z);
    __nv_bfloat16 h3 = __float2bfloat16(v.w);
    __nv_bfloat16 l0 = __float2bfloat16(v.x - __bfloat162float(h0));
    __nv_bfloat16 l1 = __float2bfloat16(v.y - __bfloat162float(h1));
    __nv_bfloat16 l2 = __float2bfloat16(v.z - __bfloat162float(h2));
    __nv_bfloat16 l3 = __float2bfloat16(v.w - __bfloat162float(h3));
    *(__nv_bfloat162*)(hi_base + half_off * 2)     = __halves2bfloat162(h0, h1);
    *(__nv_bfloat162*)(hi_base + half_off * 2 + 4) = __halves2bfloat162(h2, h3);
    *(__nv_bfloat162*)(lo_base + half_off * 2)     = __halves2bfloat162(l0, l1);
    *(__nv_bfloat162*)(lo_base + half_off * 2 + 4) = __halves2bfloat162(l2, l3);
}

__global__ void __launch_bounds__(512, 1)
k_gemm_mma(const float* __restrict__ x, const float* __restrict__ bias,
           float* __restrict__ out) {
    extern __shared__ char smem[];
    __nv_bfloat16* sAhi = (__nv_bfloat16*)(smem + OFF_AHI);
    __nv_bfloat16* sAlo = (__nv_bfloat16*)(smem + OFF_ALO);
    float* sB = (float*)(smem + OFF_BIAS);

    int tid = threadIdx.x, wid = tid >> 5, lane = tid & 31;
    int n0 = blockIdx.x * 128;

    uint32_t sWhiA = smem_u32(smem + OFF_WHI);
    uint32_t sWloA = smem_u32(smem + OFF_WLO);
    for (int idx = tid; idx < 4096; idx += 512) {
        int row = idx >> 5;
        int c   = (idx & 31) * 8;
        cp16(sWhiA + (row * W_PITCH + c) * 2, g_Whi + row * 256 + c);
        cp16(sWloA + (row * W_PITCH + c) * 2, g_Wlo + row * 256 + c);
    }
    asm volatile("cp.async.commit_group;");

    if (tid < 128) sB[tid] = bias[tid];

    // A half0: x rows
    for (int idx = tid; idx < 4096; idx += 512) {
        int row = idx >> 5;
        int k   = (idx & 31) * 4;
        int n   = n0 + row;
        if (n >= N_NODES) n = 0;
        float4 v = ((const float4*)(x + (size_t)n * D))[idx & 31];
        split_store4((char*)sAhi, (char*)sAlo, row * A_PITCH + k, v);
    }
    asm volatile("cp.async.wait_group 0;");
    __syncthreads();

    int wm = (wid & 3) * 32;
    int wn = (wid >> 2) * 32;
    int aRow = lane & 15;
    int aCol = (lane >> 4) * 8;
    int bRow = (lane & 7) | ((lane >> 1) & 8);
    int bCol = lane & 8;
    uint32_t aAhi = smem_u32(sAhi) + (uint32_t)(((wm + aRow) * A_PITCH + aCol) * 2);
    uint32_t aAlo = smem_u32(sAlo) + (uint32_t)(((wm + aRow) * A_PITCH + aCol) * 2);
    uint32_t aBhi = sWhiA + (uint32_t)(((wn + bRow) * W_PITCH + bCol) * 2);
    uint32_t aBlo = sWloA + (uint32_t)(((wn + bRow) * W_PITCH + bCol) * 2);

    float acc[2][4][4];
    #pragma unroll
    for (int mi = 0; mi < 2; mi++)
        #pragma unroll
        for (int ni = 0; ni < 4; ni++)
            #pragma unroll
            for (int q = 0; q < 4; q++) acc[mi][ni][q] = 0.0f;

    #pragma unroll
    for (int h = 0; h < 2; h++) {
        if (h == 1) {
            __syncthreads();
            // A half1: raw aggregate * mscale
            for (int idx = tid; idx < 4096; idx += 512) {
                int row = idx >> 5;
                int q   = idx & 31;
                int n   = n0 + row;
                if (n >= N_NODES) n = 0;
                float m = g_mscale[n];
                float4 v = ((const float4*)(g_agg + (size_t)n * D))[q];
                v.x *= m; v.y *= m; v.z *= m; v.w *= m;
                split_store4((char*)sAhi, (char*)sAlo, row * A_PITCH + q * 4, v);
            }
            __syncthreads();
        }
        #pragma unroll
        for (int ks = 0; ks < 8; ks++) {
            int kb = ks * 16;
            int kg = h * 128 + kb;
            uint32_t bh[2][4], bl[2][4];
            #pragma unroll
            for (int nip = 0; nip < 2; nip++) {
                uint32_t off = (uint32_t)((nip * 16 * W_PITCH + kg) * 2);
                ldsm_x4(bh[nip], aBhi + off);
                ldsm_x4(bl[nip], aBlo + off);
            }
            #pragma unroll
            for (int mi = 0; mi < 2; mi++) {
                uint32_t off = (uint32_t)((mi * 16 * A_PITCH + kb) * 2);
                uint32_t ah[4], al[4];
                ldsm_x4(ah, aAhi + off);
                ldsm_x4(al, aAlo + off);
                #pragma unroll
                for (int ni = 0; ni < 4; ni++) {
                    const uint32_t* b_hi = &bh[ni >> 1][(ni & 1) * 2];
                    const uint32_t* b_lo = &bl[ni >> 1][(ni & 1) * 2];
                    mma_bf16(acc[mi][ni], ah, b_hi);
                    mma_bf16(acc[mi][ni], ah, b_lo);
                    mma_bf16(acc[mi][ni], al, b_hi);
                }
            }
        }
    }

    int lg = lane >> 2;
    int lk = (lane & 3) * 2;
    #pragma unroll
    for (int mi = 0; mi < 2; mi++) {
        int r0 = n0 + wm + mi * 16 + lg;
        int r1 = r0 + 8;
        #pragma unroll
        for (int ni = 0; ni < 4; ni++) {
            int col = wn + ni * 8 + lk;
            float b0 = sB[col], b1 = sB[col + 1];
            if (r0 < N_NODES) {
                float2 v = {acc[mi][ni][0] + b0, acc[mi][ni][1] + b1};
                *(float2*)(out + (size_t)r0 * D + col) = v;
            }
            if (r1 < N_NODES) {
                float2 v = {acc[mi][ni][2] + b0, acc[mi][ni][3] + b1};
                *(float2*)(out + (size_t)r1 * D + col) = v;
            }
        }
    }
}

// ---------------- launch ----------------
extern "C" void kernel_launch(void* const* d_in, const int* in_sizes, int n_in,
                              void* d_out, int out_size) {
    const float* x   = (const float*)d_in[0];
    const void*  snd = d_in[1];
    const void*  rcv = d_in[2];
    const float* W   = nullptr;
    const float* b   = nullptr;
    for (int i = 3; i < n_in; i++) {
        if (in_sizes[i] == 2 * D * D) W = (const float*)d_in[i];
        else if (in_sizes[i] == D)    b = (const float*)d_in[i];
    }
    float* out = (float*)d_out;

    void *p_do = nullptr, *p_di = nullptr, *p_ov = nullptr;
    cudaGetSymbolAddress(&p_do, g_deg_out);
    cudaGetSymbolAddress(&p_di, g_deg_in);
    cudaGetSymbolAddress(&p_ov, g_ovf_cnt);
    cudaMemsetAsync(p_do, 0, sizeof(int) * N_NODES);
    cudaMemsetAsync(p_di, 0, sizeof(int) * N_NODES);
    cudaMemsetAsync(p_ov, 0, sizeof(int));

    k_probe<<<1, 32>>>(snd);
    k_wconv<<<128, 256>>>(W);
    k_ell<<<(N_EDGES + 255) / 256, 256>>>(snd, rcv);
    k_scale<<<(N_NODES + 255) / 256, 256>>>();
    k_gather<<<(N_NODES * 32 + 255) / 256, 256>>>(x);
    k_ovf<<<16, 256>>>(x);

    cudaFuncSetAttribute(k_gemm_mma, cudaFuncAttributeMaxDynamicSharedMemorySize, SMEM_K3);
    k_gemm_mma<<<(N_NODES + 127) / 128, 512, SMEM_K3>>>(x, b, out);
}

// round 9
// speedup vs baseline: 2.6303x; 1.0524x over previous
#include <cuda_runtime.h>
#include <cuda_bf16.h>
#include <stdint.h>

#define N_NODES 50000
#define N_EDGES 625000
#define D 128
#define ELLCAP 64
#define MAXOVF 4096

// ---------------- scratch (no allocs allowed) ----------------
__device__ int   g_deg_out[N_NODES];   // receiver histogram (also ELL cursor)
__device__ int   g_deg_in[N_NODES];    // sender histogram
__device__ float g_agg[(size_t)N_NODES * D];   // raw aggregate (self + edges)
__device__ int   g_is64;
__device__ __nv_bfloat16 g_Whi[128 * 256];
__device__ __nv_bfloat16 g_Wlo[128 * 256];
__device__ __align__(16) int g_ell[(size_t)N_NODES * ELLCAP];
__device__ int   g_ovf_cnt;
__device__ int   g_done;
__device__ int   g_ovf[2 * MAXOVF];

// ---------------- helpers ----------------
__device__ __forceinline__ uint32_t smem_u32(const void* p) {
    uint32_t a;
    asm("{ .reg .u64 t; cvta.to.shared.u64 t, %1; cvt.u32.u64 %0, t; }" : "=r"(a) : "l"(p));
    return a;
}
__device__ __forceinline__ void ldsm_x4(uint32_t* r, uint32_t addr) {
    asm volatile("ldmatrix.sync.aligned.m8n8.x4.shared.b16 {%0,%1,%2,%3}, [%4];"
                 : "=r"(r[0]), "=r"(r[1]), "=r"(r[2]), "=r"(r[3]) : "r"(addr));
}
__device__ __forceinline__ void cp16(uint32_t dst, const void* src) {
    asm volatile("cp.async.cg.shared.global [%0], [%1], 16;" :: "r"(dst), "l"(src));
}
__device__ __forceinline__ void mma_bf16(float* c, const uint32_t* a, const uint32_t* b) {
    asm volatile(
        "mma.sync.aligned.m16n8k16.row.col.f32.bf16.bf16.f32 "
        "{%0,%1,%2,%3}, {%4,%5,%6,%7}, {%8,%9}, {%0,%1,%2,%3};"
        : "+f"(c[0]), "+f"(c[1]), "+f"(c[2]), "+f"(c[3])
        : "r"(a[0]), "r"(a[1]), "r"(a[2]), "r"(a[3]), "r"(b[0]), "r"(b[1]));
}
__device__ __forceinline__ int load_idx(const void* p, int e, int is64) {
    return is64 ? (int)((const long long*)p)[e] : ((const int*)p)[e];
}

// ---------------- K0: fused init (zero + probe + W split) ----------------
__global__ void k_init(const void* __restrict__ senders, const float* __restrict__ W) {
    int i = blockIdx.x * blockDim.x + threadIdx.x;
    int stride = gridDim.x * blockDim.x;
    for (int j = i; j < N_NODES; j += stride) { g_deg_out[j] = 0; g_deg_in[j] = 0; }
    for (int j = i; j < 128 * 256; j += stride) {
        float v = W[j];
        __nv_bfloat16 h = __float2bfloat16(v);
        g_Whi[j] = h;
        g_Wlo[j] = __float2bfloat16(v - __bfloat162float(h));
    }
    if (i == 0) {
        g_ovf_cnt = 0;
        g_done = 0;
        const int* w = (const int*)senders;
        int is64 = 1;
        #pragma unroll
        for (int k = 0; k < 16; k++) if (w[2 * k + 1] != 0) is64 = 0;
        g_is64 = is64;
    }
}

// ---------------- K1: fused degree count + ELL bucket fill ----------------
__global__ void k_ell(const void* __restrict__ senders, const void* __restrict__ receivers) {
    int e = blockIdx.x * blockDim.x + threadIdx.x;
    if (e >= N_EDGES) return;
    int is64 = g_is64;
    int s = load_idx(senders, e, is64);
    int r = load_idx(receivers, e, is64);
    atomicAdd(&g_deg_in[s], 1);
    int pos = atomicAdd(&g_deg_out[r], 1);       // histogram == cursor
    if (pos < ELLCAP) {
        g_ell[(size_t)r * ELLCAP + pos] = s;
    } else {
        int o = atomicAdd(&g_ovf_cnt, 1);
        if (o < MAXOVF) { g_ovf[2 * o] = r; g_ovf[2 * o + 1] = s; }
    }
}

// ---------------- K2: gather (1 warp/node, inline scales, 4-way MLP) ----------------
__global__ void __launch_bounds__(256) k_gather(const float* __restrict__ x) {
    __shared__ int sdone;
    int w = (blockIdx.x * blockDim.x + threadIdx.x) >> 5;
    int lane = threadIdx.x & 31;

    if (w < N_NODES) {
        int deg_full = g_deg_out[w];
        int deg = deg_full > ELLCAP ? ELLCAP : deg_full;
        const int4* row4 = (const int4*)(g_ell + (size_t)w * ELLCAP);

        // self-loop term: sender scale = rsqrt(deg_out[w]+1)
        float ss = rsqrtf((float)(deg_full + 1));
        float4 acc = ((const float4*)(x + (size_t)w * D))[lane];
        acc.x *= ss; acc.y *= ss; acc.z *= ss; acc.w *= ss;
        float4 acc2 = {0.f, 0.f, 0.f, 0.f};

        int j = 0;
        for (; j + 3 < deg; j += 4) {
            int4 s4 = row4[j >> 2];
            int d0 = g_deg_out[s4.x], d1 = g_deg_out[s4.y];
            int d2 = g_deg_out[s4.z], d3 = g_deg_out[s4.w];
            float4 v0 = ((const float4*)(x + (size_t)s4.x * D))[lane];
            float4 v1 = ((const float4*)(x + (size_t)s4.y * D))[lane];
            float4 v2 = ((const float4*)(x + (size_t)s4.z * D))[lane];
            float4 v3 = ((const float4*)(x + (size_t)s4.w * D))[lane];
            float c0 = rsqrtf((float)(d0 + 1));
            float c1 = rsqrtf((float)(d1 + 1));
            float c2 = rsqrtf((float)(d2 + 1));
            float c3 = rsqrtf((float)(d3 + 1));
            acc.x  += v0.x * c0; acc.y  += v0.y * c0; acc.z  += v0.z * c0; acc.w  += v0.w * c0;
            acc2.x += v1.x * c1; acc2.y += v1.y * c1; acc2.z += v1.z * c1; acc2.w += v1.w * c1;
            acc.x  += v2.x * c2; acc.y  += v2.y * c2; acc.z  += v2.z * c2; acc.w  += v2.w * c2;
            acc2.x += v3.x * c3; acc2.y += v3.y * c3; acc2.z += v3.z * c3; acc2.w += v3.w * c3;
        }
        for (; j < deg; j++) {
            int s0 = g_ell[(size_t)w * ELLCAP + j];
            float c0 = rsqrtf((float)(g_deg_out[s0] + 1));
            float4 v0 = ((const float4*)(x + (size_t)s0 * D))[lane];
            acc.x += v0.x * c0; acc.y += v0.y * c0; acc.z += v0.z * c0; acc.w += v0.w * c0;
        }
        float4 r;
        r.x = acc.x + acc2.x;
        r.y = acc.y + acc2.y;
        r.z = acc.z + acc2.z;
        r.w = acc.w + acc2.w;
        ((float4*)(g_agg + (size_t)w * D))[lane] = r;   // unscaled; mscale in GEMM
    }

    // ---- last-done block applies overflow list (normally empty) ----
    __syncthreads();
    if (threadIdx.x == 0) {
        __threadfence();
        int t = atomicAdd(&g_done, 1);
        sdone = (t == (int)gridDim.x - 1) ? 1 : 0;
    }
    __syncthreads();
    if (sdone) {
        int cnt = g_ovf_cnt;
        if (cnt > MAXOVF) cnt = MAXOVF;
        int warp = threadIdx.x >> 5;
        for (int o = warp; o < cnt; o += 8) {
            int r = g_ovf[2 * o], s = g_ovf[2 * o + 1];
            float c = rsqrtf((float)(g_deg_out[s] + 1));
            float4 v = ((const float4*)(x + (size_t)s * D))[lane];
            v.x *= c; v.y *= c; v.z *= c; v.w *= c;
            float* dst = g_agg + (size_t)r * D + lane * 4;
            asm volatile("red.global.add.v4.f32 [%0], {%1,%2,%3,%4};"
                         :: "l"(dst), "f"(v.x), "f"(v.y), "f"(v.z), "f"(v.w) : "memory");
        }
    }
}

// ---------------- K3: split-bf16 GEMM (512 thr, ldmatrix, cp.async W) ----------------
#define A_PITCH 136
#define W_PITCH 264
#define OFF_WHI  0
#define OFF_WLO  (OFF_WHI + 128 * W_PITCH * 2)
#define OFF_AHI  (OFF_WLO + 128 * W_PITCH * 2)
#define OFF_ALO  (OFF_AHI + 128 * A_PITCH * 2)
#define OFF_BIAS (OFF_ALO + 128 * A_PITCH * 2)
#define OFF_MS   (OFF_BIAS + 512)
#define SMEM_K3  (OFF_MS + 512)

__device__ __forceinline__ void split_store4(char* hi_base, char* lo_base, int half_off, float4 v) {
    __nv_bfloat16 h0 = __float2bfloat16(v.x);
    __nv_bfloat16 h1 = __float2bfloat16(v.y);
    __nv_bfloat16 h2 = __float2bfloat16(v.z);
    __nv_bfloat16 h3 = __float2bfloat16(v.w);
    __nv_bfloat16 l0 = __float2bfloat16(v.x - __bfloat162float(h0));
    __nv_bfloat16 l1 = __float2bfloat16(v.y - __bfloat162float(h1));
    __nv_bfloat16 l2 = __float2bfloat16(v.z - __bfloat162float(h2));
    __nv_bfloat16 l3 = __float2bfloat16(v.w - __bfloat162float(h3));
    *(__nv_bfloat162*)(hi_base + half_off * 2)     = __halves2bfloat162(h0, h1);
    *(__nv_bfloat162*)(hi_base + half_off * 2 + 4) = __halves2bfloat162(h2, h3);
    *(__nv_bfloat162*)(lo_base + half_off * 2)     = __halves2bfloat162(l0, l1);
    *(__nv_bfloat162*)(lo_base + half_off * 2 + 4) = __halves2bfloat162(l2, l3);
}

__global__ void __launch_bounds__(512, 1)
k_gemm_mma(const float* __restrict__ x, const float* __restrict__ bias,
           float* __restrict__ out) {
    extern __shared__ char smem[];
    __nv_bfloat16* sAhi = (__nv_bfloat16*)(smem + OFF_AHI);
    __nv_bfloat16* sAlo = (__nv_bfloat16*)(smem + OFF_ALO);
    float* sB = (float*)(smem + OFF_BIAS);
    float* sM = (float*)(smem + OFF_MS);

    int tid = threadIdx.x, wid = tid >> 5, lane = tid & 31;
    int n0 = blockIdx.x * 128;

    uint32_t sWhiA = smem_u32(smem + OFF_WHI);
    uint32_t sWloA = smem_u32(smem + OFF_WLO);
    for (int idx = tid; idx < 4096; idx += 512) {
        int row = idx >> 5;
        int c   = (idx & 31) * 8;
        cp16(sWhiA + (row * W_PITCH + c) * 2, g_Whi + row * 256 + c);
        cp16(sWloA + (row * W_PITCH + c) * 2, g_Wlo + row * 256 + c);
    }
    asm volatile("cp.async.commit_group;");

    if (tid < 128) {
        sB[tid] = bias[tid];
        int n = n0 + tid;
        if (n >= N_NODES) n = 0;
        float dout = (float)(g_deg_out[n] + 1);
        float din  = (float)(g_deg_in[n] + 1);
        sM[tid] = rsqrtf(din) / dout;        // mscale
    }

    // A half0: x rows
    for (int idx = tid; idx < 4096; idx += 512) {
        int row = idx >> 5;
        int k   = (idx & 31) * 4;
        int n   = n0 + row;
        if (n >= N_NODES) n = 0;
        float4 v = ((const float4*)(x + (size_t)n * D))[idx & 31];
        split_store4((char*)sAhi, (char*)sAlo, row * A_PITCH + k, v);
    }
    asm volatile("cp.async.wait_group 0;");
    __syncthreads();

    int wm = (wid & 3) * 32;
    int wn = (wid >> 2) * 32;
    int aRow = lane & 15;
    int aCol = (lane >> 4) * 8;
    int bRow = (lane & 7) | ((lane >> 1) & 8);
    int bCol = lane & 8;
    uint32_t aAhi = smem_u32(sAhi) + (uint32_t)(((wm + aRow) * A_PITCH + aCol) * 2);
    uint32_t aAlo = smem_u32(sAlo) + (uint32_t)(((wm + aRow) * A_PITCH + aCol) * 2);
    uint32_t aBhi = sWhiA + (uint32_t)(((wn + bRow) * W_PITCH + bCol) * 2);
    uint32_t aBlo = sWloA + (uint32_t)(((wn + bRow) * W_PITCH + bCol) * 2);

    float acc[2][4][4];
    #pragma unroll
    for (int mi = 0; mi < 2; mi++)
        #pragma unroll
        for (int ni = 0; ni < 4; ni++)
            #pragma unroll
            for (int q = 0; q < 4; q++) acc[mi][ni][q] = 0.0f;

    #pragma unroll
    for (int h = 0; h < 2; h++) {
        if (h == 1) {
            __syncthreads();
            // A half1: raw aggregate * mscale
            for (int idx = tid; idx < 4096; idx += 512) {
                int row = idx >> 5;
                int q   = idx & 31;
                int n   = n0 + row;
                if (n >= N_NODES) n = 0;
                float m = sM[row];
                float4 v = ((const float4*)(g_agg + (size_t)n * D))[q];
                v.x *= m; v.y *= m; v.z *= m; v.w *= m;
                split_store4((char*)sAhi, (char*)sAlo, row * A_PITCH + q * 4, v);
            }
            __syncthreads();
        }
        #pragma unroll
        for (int ks = 0; ks < 8; ks++) {
            int kb = ks * 16;
            int kg = h * 128 + kb;
            uint32_t bh[2][4], bl[2][4];
            #pragma unroll
            for (int nip = 0; nip < 2; nip++) {
                uint32_t off = (uint32_t)((nip * 16 * W_PITCH + kg) * 2);
                ldsm_x4(bh[nip], aBhi + off);
                ldsm_x4(bl[nip], aBlo + off);
            }
            #pragma unroll
            for (int mi = 0; mi < 2; mi++) {
                uint32_t off = (uint32_t)((mi * 16 * A_PITCH + kb) * 2);
                uint32_t ah[4], al[4];
                ldsm_x4(ah, aAhi + off);
                ldsm_x4(al, aAlo + off);
                #pragma unroll
                for (int ni = 0; ni < 4; ni++) {
                    const uint32_t* b_hi = &bh[ni >> 1][(ni & 1) * 2];
                    const uint32_t* b_lo = &bl[ni >> 1][(ni & 1) * 2];
                    mma_bf16(acc[mi][ni], ah, b_hi);
                    mma_bf16(acc[mi][ni], ah, b_lo);
                    mma_bf16(acc[mi][ni], al, b_hi);
                }
            }
        }
    }

    int lg = lane >> 2;
    int lk = (lane & 3) * 2;
    #pragma unroll
    for (int mi = 0; mi < 2; mi++) {
        int r0 = n0 + wm + mi * 16 + lg;
        int r1 = r0 + 8;
        #pragma unroll
        for (int ni = 0; ni < 4; ni++) {
            int col = wn + ni * 8 + lk;
            float b0 = sB[col], b1 = sB[col + 1];
            if (r0 < N_NODES) {
                float2 v = {acc[mi][ni][0] + b0, acc[mi][ni][1] + b1};
                *(float2*)(out + (size_t)r0 * D + col) = v;
            }
            if (r1 < N_NODES) {
                float2 v = {acc[mi][ni][2] + b0, acc[mi][ni][3] + b1};
                *(float2*)(out + (size_t)r1 * D + col) = v;
            }
        }
    }
}

// ---------------- launch ----------------
extern "C" void kernel_launch(void* const* d_in, const int* in_sizes, int n_in,
                              void* d_out, int out_size) {
    const float* x   = (const float*)d_in[0];
    const void*  snd = d_in[1];
    const void*  rcv = d_in[2];
    const float* W   = nullptr;
    const float* b   = nullptr;
    for (int i = 3; i < n_in; i++) {
        if (in_sizes[i] == 2 * D * D) W = (const float*)d_in[i];
        else if (in_sizes[i] == D)    b = (const float*)d_in[i];
    }
    float* out = (float*)d_out;

    k_init<<<148, 256>>>(snd, W);
    k_ell<<<(N_EDGES + 255) / 256, 256>>>(snd, rcv);
    k_gather<<<(N_NODES * 32 + 255) / 256, 256>>>(x);

    cudaFuncSetAttribute(k_gemm_mma, cudaFuncAttributeMaxDynamicSharedMemorySize, SMEM_K3);
    k_gemm_mma<<<(N_NODES + 127) / 128, 512, SMEM_K3>>>(x, b, out);
}

// round 11
// speedup vs baseline: 2.8550x; 1.0854x over previous
#include <cuda_runtime.h>
#include <cuda_fp16.h>
#include <stdint.h>

#define N_NODES 50000
#define N_EDGES 625000
#define D 128
#define ELLCAP 64
#define MAXOVF 4096

// ---------------- scratch (no allocs allowed) ----------------
__device__ int   g_deg_out[N_NODES];   // receiver histogram (also ELL cursor)
__device__ int   g_deg_in[N_NODES];    // sender histogram
__device__ float g_agg[(size_t)N_NODES * D];   // raw aggregate (self + edges)
__device__ int   g_is64;
__device__ __half g_Whi[128 * 256];    // W fp16 hi (row-major [N][K])
__device__ __half g_Wlo[128 * 256];    // W fp16 lo
__device__ __align__(16) int g_ell[(size_t)N_NODES * ELLCAP];
__device__ int   g_ovf_cnt;
__device__ int   g_done;
__device__ int   g_ovf[2 * MAXOVF];

// ---------------- helpers ----------------
__device__ __forceinline__ uint32_t smem_u32(const void* p) {
    uint32_t a;
    asm("{ .reg .u64 t; cvta.to.shared.u64 t, %1; cvt.u32.u64 %0, t; }" : "=r"(a) : "l"(p));
    return a;
}
__device__ __forceinline__ void ldsm_x4(uint32_t* r, uint32_t addr) {
    asm volatile("ldmatrix.sync.aligned.m8n8.x4.shared.b16 {%0,%1,%2,%3}, [%4];"
                 : "=r"(r[0]), "=r"(r[1]), "=r"(r[2]), "=r"(r[3]) : "r"(addr));
}
__device__ __forceinline__ void cp16(uint32_t dst, const void* src) {
    asm volatile("cp.async.cg.shared.global [%0], [%1], 16;" :: "r"(dst), "l"(src));
}
__device__ __forceinline__ void mma_f16(float* c, const uint32_t* a, const uint32_t* b) {
    asm volatile(
        "mma.sync.aligned.m16n8k16.row.col.f32.f16.f16.f32 "
        "{%0,%1,%2,%3}, {%4,%5,%6,%7}, {%8,%9}, {%0,%1,%2,%3};"
        : "+f"(c[0]), "+f"(c[1]), "+f"(c[2]), "+f"(c[3])
        : "r"(a[0]), "r"(a[1]), "r"(a[2]), "r"(a[3]), "r"(b[0]), "r"(b[1]));
}
__device__ __forceinline__ int load_idx(const void* p, int e, int is64) {
    return is64 ? (int)((const long long*)p)[e] : ((const int*)p)[e];
}

// ---------------- K0: fused init (zero + probe + W fp16 split) ----------------
__global__ void k_init(const void* __restrict__ senders, const float* __restrict__ W) {
    int i = blockIdx.x * blockDim.x + threadIdx.x;
    int stride = gridDim.x * blockDim.x;
    for (int j = i; j < N_NODES; j += stride) { g_deg_out[j] = 0; g_deg_in[j] = 0; }
    for (int j = i; j < 128 * 256; j += stride) {
        float v = W[j];
        __half h = __float2half(v);
        g_Whi[j] = h;
        g_Wlo[j] = __float2half(v - __half2float(h));
    }
    if (i == 0) {
        g_ovf_cnt = 0;
        g_done = 0;
        const int* w = (const int*)senders;
        int is64 = 1;
        #pragma unroll
        for (int k = 0; k < 16; k++) if (w[2 * k + 1] != 0) is64 = 0;
        g_is64 = is64;
    }
}

// ---------------- K1: fused degree count + ELL bucket fill ----------------
__global__ void k_ell(const void* __restrict__ senders, const void* __restrict__ receivers) {
    int e = blockIdx.x * blockDim.x + threadIdx.x;
    if (e >= N_EDGES) return;
    int is64 = g_is64;
    int s = load_idx(senders, e, is64);
    int r = load_idx(receivers, e, is64);
    atomicAdd(&g_deg_in[s], 1);
    int pos = atomicAdd(&g_deg_out[r], 1);       // histogram == cursor
    if (pos < ELLCAP) {
        g_ell[(size_t)r * ELLCAP + pos] = s;
    } else {
        int o = atomicAdd(&g_ovf_cnt, 1);
        if (o < MAXOVF) { g_ovf[2 * o] = r; g_ovf[2 * o + 1] = s; }
    }
}

// ---------------- K2: gather (1 warp/node, inline scales, 4-way MLP) ----------------
__global__ void __launch_bounds__(256) k_gather(const float* __restrict__ x) {
    __shared__ int sdone;
    int w = (blockIdx.x * blockDim.x + threadIdx.x) >> 5;
    int lane = threadIdx.x & 31;

    if (w < N_NODES) {
        int deg_full = g_deg_out[w];
        int deg = deg_full > ELLCAP ? ELLCAP : deg_full;
        const int4* row4 = (const int4*)(g_ell + (size_t)w * ELLCAP);

        float ss = rsqrtf((float)(deg_full + 1));
        float4 acc = ((const float4*)(x + (size_t)w * D))[lane];
        acc.x *= ss; acc.y *= ss; acc.z *= ss; acc.w *= ss;
        float4 acc2 = {0.f, 0.f, 0.f, 0.f};

        int j = 0;
        for (; j + 3 < deg; j += 4) {
            int4 s4 = row4[j >> 2];
            int d0 = g_deg_out[s4.x], d1 = g_deg_out[s4.y];
            int d2 = g_deg_out[s4.z], d3 = g_deg_out[s4.w];
            float4 v0 = ((const float4*)(x + (size_t)s4.x * D))[lane];
            float4 v1 = ((const float4*)(x + (size_t)s4.y * D))[lane];
            float4 v2 = ((const float4*)(x + (size_t)s4.z * D))[lane];
            float4 v3 = ((const float4*)(x + (size_t)s4.w * D))[lane];
            float c0 = rsqrtf((float)(d0 + 1));
            float c1 = rsqrtf((float)(d1 + 1));
            float c2 = rsqrtf((float)(d2 + 1));
            float c3 = rsqrtf((float)(d3 + 1));
            acc.x  += v0.x * c0; acc.y  += v0.y * c0; acc.z  += v0.z * c0; acc.w  += v0.w * c0;
            acc2.x += v1.x * c1; acc2.y += v1.y * c1; acc2.z += v1.z * c1; acc2.w += v1.w * c1;
            acc.x  += v2.x * c2; acc.y  += v2.y * c2; acc.z  += v2.z * c2; acc.w  += v2.w * c2;
            acc2.x += v3.x * c3; acc2.y += v3.y * c3; acc2.z += v3.z * c3; acc2.w += v3.w * c3;
        }
        for (; j < deg; j++) {
            int s0 = g_ell[(size_t)w * ELLCAP + j];
            float c0 = rsqrtf((float)(g_deg_out[s0] + 1));
            float4 v0 = ((const float4*)(x + (size_t)s0 * D))[lane];
            acc.x += v0.x * c0; acc.y += v0.y * c0; acc.z += v0.z * c0; acc.w += v0.w * c0;
        }
        float4 r;
        r.x = acc.x + acc2.x;
        r.y = acc.y + acc2.y;
        r.z = acc.z + acc2.z;
        r.w = acc.w + acc2.w;
        ((float4*)(g_agg + (size_t)w * D))[lane] = r;   // unscaled; mscale in GEMM
    }

    // ---- last-done block applies overflow list (normally empty) ----
    __syncthreads();
    if (threadIdx.x == 0) {
        __threadfence();
        int t = atomicAdd(&g_done, 1);
        sdone = (t == (int)gridDim.x - 1) ? 1 : 0;
    }
    __syncthreads();
    if (sdone) {
        int cnt = g_ovf_cnt;
        if (cnt > MAXOVF) cnt = MAXOVF;
        int warp = threadIdx.x >> 5;
        for (int o = warp; o < cnt; o += 8) {
            int r = g_ovf[2 * o], s = g_ovf[2 * o + 1];
            float c = rsqrtf((float)(g_deg_out[s] + 1));
            float4 v = ((const float4*)(x + (size_t)s * D))[lane];
            v.x *= c; v.y *= c; v.z *= c; v.w *= c;
            float* dst = g_agg + (size_t)r * D + lane * 4;
            asm volatile("red.global.add.v4.f32 [%0], {%1,%2,%3,%4};"
                         :: "l"(dst), "f"(v.x), "f"(v.y), "f"(v.z), "f"(v.w) : "memory");
        }
    }
}

// ---------------- K3: fp16 2-term GEMM (512 thr, full-K A, single mainloop) ----------------
// out = [x | agg*m] @ (Wh + Wl)^T + b ; A converted once to fp16 (K=256 panel).
#define A_PITCH 264            // halves per A row (256 + 8 pad), 528B
#define W_PITCH 264
#define OFF_WHI  0
#define OFF_WLO  (OFF_WHI + 128 * W_PITCH * 2)       // 67584
#define OFF_A    (OFF_WLO + 128 * W_PITCH * 2)       // 135168
#define OFF_BIAS (OFF_A   + 128 * A_PITCH * 2)       // 202752
#define OFF_MS   (OFF_BIAS + 512)
#define SMEM_K3  (OFF_MS + 512)                      // 203776 bytes

__device__ __forceinline__ void h4_store(char* base, int half_off, float4 v) {
    __half2 p0 = __floats2half2_rn(v.x, v.y);
    __half2 p1 = __floats2half2_rn(v.z, v.w);
    *(__half2*)(base + half_off * 2)     = p0;
    *(__half2*)(base + half_off * 2 + 4) = p1;
}

__global__ void __launch_bounds__(512, 1)
k_gemm_mma(const float* __restrict__ x, const float* __restrict__ bias,
           float* __restrict__ out) {
    extern __shared__ char smem[];
    __half* sA = (__half*)(smem + OFF_A);
    float* sB = (float*)(smem + OFF_BIAS);
    float* sM = (float*)(smem + OFF_MS);

    int tid = threadIdx.x, wid = tid >> 5, lane = tid & 31;
    int n0 = blockIdx.x * 128;

    // W fill via cp.async (overlaps everything below)
    uint32_t sWhiA = smem_u32(smem + OFF_WHI);
    uint32_t sWloA = smem_u32(smem + OFF_WLO);
    for (int idx = tid; idx < 4096; idx += 512) {
        int row = idx >> 5;
        int c   = (idx & 31) * 8;
        cp16(sWhiA + (row * W_PITCH + c) * 2, g_Whi + row * 256 + c);
        cp16(sWloA + (row * W_PITCH + c) * 2, g_Wlo + row * 256 + c);
    }
    asm volatile("cp.async.commit_group;");

    if (tid < 128) {
        sB[tid] = bias[tid];
        int n = n0 + tid;
        if (n >= N_NODES) n = 0;
        float dout = (float)(g_deg_out[n] + 1);
        float din  = (float)(g_deg_in[n] + 1);
        sM[tid] = rsqrtf(din) / dout;        // mscale
    }
    __syncthreads();                          // sM visible to conversion loop

    // A conversion: full K=256 panel (k<128: x ; k>=128: agg * mscale)
    for (int idx = tid; idx < 8192; idx += 512) {
        int row = idx >> 6;
        int q   = idx & 63;
        int n   = n0 + row;
        if (n >= N_NODES) n = 0;
        float4 v;
        if (q < 32) {
            v = ((const float4*)(x + (size_t)n * D))[q];
        } else {
            float m = sM[row];
            v = ((const float4*)(g_agg + (size_t)n * D))[q - 32];
            v.x *= m; v.y *= m; v.z *= m; v.w *= m;
        }
        h4_store((char*)sA, row * A_PITCH + q * 4, v);
    }
    asm volatile("cp.async.wait_group 0;");
    __syncthreads();

    // warp tiling: 4 (M) x 4 (N); warp tile 32M x 32N
    int wm = (wid & 3) * 32;
    int wn = (wid >> 2) * 32;
    int aRow = lane & 15;
    int aCol = (lane >> 4) * 8;
    int bRow = (lane & 7) | ((lane >> 1) & 8);
    int bCol = lane & 8;
    uint32_t aA   = smem_u32(sA) + (uint32_t)(((wm + aRow) * A_PITCH + aCol) * 2);
    uint32_t aBhi = sWhiA + (uint32_t)(((wn + bRow) * W_PITCH + bCol) * 2);
    uint32_t aBlo = sWloA + (uint32_t)(((wn + bRow) * W_PITCH + bCol) * 2);

    float acc[2][4][4];
    #pragma unroll
    for (int mi = 0; mi < 2; mi++)
        #pragma unroll
        for (int ni = 0; ni < 4; ni++)
            #pragma unroll
            for (int q = 0; q < 4; q++) acc[mi][ni][q] = 0.0f;

    #pragma unroll
    for (int ks = 0; ks < 16; ks++) {
        int kb = ks * 16;
        uint32_t bh[2][4], bl[2][4];
        #pragma unroll
        for (int nip = 0; nip < 2; nip++) {
            uint32_t off = (uint32_t)((nip * 16 * W_PITCH + kb) * 2);
            ldsm_x4(bh[nip], aBhi + off);
            ldsm_x4(bl[nip], aBlo + off);
        }
        #pragma unroll
        for (int mi = 0; mi < 2; mi++) {
            uint32_t off = (uint32_t)((mi * 16 * A_PITCH + kb) * 2);
            uint32_t ah[4];
            ldsm_x4(ah, aA + off);
            #pragma unroll
            for (int ni = 0; ni < 4; ni++) {
                const uint32_t* b_hi = &bh[ni >> 1][(ni & 1) * 2];
                const uint32_t* b_lo = &bl[ni >> 1][(ni & 1) * 2];
                mma_f16(acc[mi][ni], ah, b_hi);
                mma_f16(acc[mi][ni], ah, b_lo);
            }
        }
    }

    int lg = lane >> 2;
    int lk = (lane & 3) * 2;
    #pragma unroll
    for (int mi = 0; mi < 2; mi++) {
        int r0 = n0 + wm + mi * 16 + lg;
        int r1 = r0 + 8;
        #pragma unroll
        for (int ni = 0; ni < 4; ni++) {
            int col = wn + ni * 8 + lk;
            float b0 = sB[col], b1 = sB[col + 1];
            if (r0 < N_NODES) {
                float2 v = {acc[mi][ni][0] + b0, acc[mi][ni][1] + b1};
                *(float2*)(out + (size_t)r0 * D + col) = v;
            }
            if (r1 < N_NODES) {
                float2 v = {acc[mi][ni][2] + b0, acc[mi][ni][3] + b1};
                *(float2*)(out + (size_t)r1 * D + col) = v;
            }
        }
    }
}

// ---------------- launch ----------------
extern "C" void kernel_launch(void* const* d_in, const int* in_sizes, int n_in,
                              void* d_out, int out_size) {
    const float* x   = (const float*)d_in[0];
    const void*  snd = d_in[1];
    const void*  rcv = d_in[2];
    const float* W   = nullptr;
    const float* b   = nullptr;
    for (int i = 3; i < n_in; i++) {
        if (in_sizes[i] == 2 * D * D) W = (const float*)d_in[i];
        else if (in_sizes[i] == D)    b = (const float*)d_in[i];
    }
    float* out = (float*)d_out;

    k_init<<<148, 256>>>(snd, W);
    k_ell<<<(N_EDGES + 255) / 256, 256>>>(snd, rcv);
    k_gather<<<(N_NODES * 32 + 255) / 256, 256>>>(x);

    cudaFuncSetAttribute(k_gemm_mma, cudaFuncAttributeMaxDynamicSharedMemorySize, SMEM_K3);
    k_gemm_mma<<<(N_NODES + 127) / 128, 512, SMEM_K3>>>(x, b, out);
}